// round 12
// baseline (speedup 1.0000x reference)
#include <cuda_runtime.h>
#include <cuda_bf16.h>
#include <math.h>

#define NP      147456      // 16*96*96
#define HW      9216        // 96*96
#define CDIM    512
#define KP      64          // protos per side
#define NSEL    256
#define NREF    10
#define TAU     0.07f
#define MARGIN  0.2f
#define MBLEND  0.3f

#define NCAND   3072        // approx-candidate target per side
#define CAP     4096        // candidate buffer cap

// ---------------- scratch ----------------
__device__ float    g_Wt[CDIM * 128];         // [c][j] fp32 transposed protos (rescore)
__device__ unsigned g_Wb16u[128 * 256];       // [proto][ch-pair] bf16x2 protos
__device__ float    g_score[2][NP];           // approx scores (bf16 MMA)
__device__ unsigned g_hist16[2][65536];
__device__ unsigned g_hist8[2][256];
__device__ int      g_thr16[2];
__device__ int      g_rem[2];
__device__ unsigned g_thr24[2];
__device__ int      g_ccnt[2];
__device__ int      g_cand[2][CAP];
__device__ float    g_cscore[2][CAP];
__device__ int      g_idx[2][NSEL];
__device__ float    g_feats[2][NSEL * CDIM];
__device__ float    g_p[2][KP * CDIM];
__device__ int      g_assign[2][NSEL];
__device__ float    g_simpos[NSEL], g_simneg[NSEL], g_info[NSEL];

// ---------------- grid barrier (persistent kernels; blocks << 148 SMs) ----------------
__device__ unsigned g_barcnt = 0;
__device__ volatile unsigned g_bargen = 0;
__device__ __forceinline__ void grid_barrier(unsigned nblk) {
    __syncthreads();
    if (threadIdx.x == 0) {
        __threadfence();
        unsigned gen = g_bargen;
        if (atomicAdd(&g_barcnt, 1u) == nblk - 1u) {
            atomicExch(&g_barcnt, 0u);
            __threadfence();
            g_bargen = gen + 1u;
        } else {
            while (g_bargen == gen) { }
            __threadfence();
        }
    }
    __syncthreads();
}

// ---------------- helpers ----------------
__device__ __forceinline__ unsigned mapf(float x) {
    unsigned u = __float_as_uint(x);
    return (u & 0x80000000u) ? ~u : (u | 0x80000000u);
}
__device__ __forceinline__ unsigned pack_bf2(float lo, float hi) {
    unsigned r;
    asm("cvt.rn.bf16x2.f32 %0, %1, %2;" : "=r"(r) : "f"(hi), "f"(lo));
    return r;
}
__device__ __forceinline__ void mma16816(float* c, const unsigned* a, unsigned b0, unsigned b1) {
    asm volatile("mma.sync.aligned.m16n8k16.row.col.f32.bf16.bf16.f32 "
                 "{%0,%1,%2,%3}, {%4,%5,%6,%7}, {%8,%9}, {%0,%1,%2,%3};"
                 : "+f"(c[0]), "+f"(c[1]), "+f"(c[2]), "+f"(c[3])
                 : "r"(a[0]), "r"(a[1]), "r"(a[2]), "r"(a[3]), "r"(b0), "r"(b1));
}
__device__ __forceinline__ unsigned sptr(const void* p) {
    return (unsigned)__cvta_generic_to_shared(p);
}
__device__ __forceinline__ void cp16_cg(unsigned s, const void* g) {
    asm volatile("cp.async.cg.shared.global [%0], [%1], 16;" :: "r"(s), "l"(g));
}
__device__ __forceinline__ void cp16_ca(unsigned s, const void* g) {
    asm volatile("cp.async.ca.shared.global [%0], [%1], 16;" :: "r"(s), "l"(g));
}

// ---------------- kernel 1: prep (Wt transpose + bf16 pack + zero hists) ----------------
__global__ void prep_all(const float* __restrict__ fg, const float* __restrict__ bg) {
    int gid = blockIdx.x * 256 + threadIdx.x;   // 65536 threads
    // zero hist16 (131072 words)
    ((unsigned*)&g_hist16[0][0])[gid] = 0u;
    ((unsigned*)&g_hist16[0][0])[gid + 65536] = 0u;
    // zero hist8 + ccnt
    if (gid < 512) (&g_hist8[0][0])[gid] = 0u;
    if (gid < 2) g_ccnt[gid] = 0;
    // Wt transpose: g_Wt[c*128+j] = proto[j][c]
    {
        int c = gid >> 7, j = gid & 127;
        float v = (j < KP) ? fg[j * CDIM + c] : bg[(j - KP) * CDIM + c];
        g_Wt[gid] = v;
    }
    // bf16 pack: 32768 u32
    if (gid < 32768) {
        int j = gid >> 8, cp = gid & 255;
        const float* src = (j < KP) ? (fg + j * CDIM) : (bg + (j - KP) * CDIM);
        g_Wb16u[gid] = pack_bf2(src[cp * 2], src[cp * 2 + 1]);
    }
}

// ---------------- kernel 2: approx score (bf16 TC, cp.async double-buffered) ----------------
#define SCORE_SMEM (32768 + 20480 + 10240 + 512)
__global__ __launch_bounds__(256, 2) void score_tc(
    const float* __restrict__ F, const float* __restrict__ M) {
    extern __shared__ char smem_raw[];
    float*    Af32   = (float*)smem_raw;
    unsigned* Wst    = (unsigned*)(smem_raw + 32768);
    unsigned* As32   = (unsigned*)(smem_raw + 32768 + 20480);
    float*    normsh = (float*)(smem_raw + 63488);

    int tid = threadIdx.x, lane = tid & 31, w = tid >> 5;
    int wm = w >> 1, wn = w & 1;
    int gpix0 = blockIdx.x * 128;
    int n = gpix0 / HW, hw0 = gpix0 - n * HW;
    const float* Fb = F + (size_t)n * CDIM * HW + hw0;

    if (tid < 128) normsh[tid] = 0.f;

    float acc[2][8][4];
#pragma unroll
    for (int a = 0; a < 2; a++)
#pragma unroll
        for (int b = 0; b < 8; b++)
#pragma unroll
            for (int d = 0; d < 4; d++) acc[a][b][d] = 0.f;

    int px = tid & 127, half = tid >> 7;
    float mynrm = 0.f;

    auto issue_chunk = [&](int ic) {
        int buf = ic & 1;
        int c0 = ic * 32;
        float* Ad = Af32 + buf * (32 * 128);
#pragma unroll
        for (int j = 0; j < 4; j++) {
            int idx = tid + 256 * j;
            int r = idx >> 5, sg = idx & 31;
            cp16_cg(sptr(Ad + r * 128 + sg * 4),
                    Fb + (size_t)(c0 + r) * HW + sg * 4);
        }
        unsigned* Wd = Wst + buf * (128 * 20);
#pragma unroll
        for (int j = 0; j < 2; j++) {
            int idx = tid + 256 * j;
            int p = idx >> 2, sg = idx & 3;
            cp16_ca(sptr(Wd + p * 20 + sg * 4),
                    g_Wb16u + p * 256 + (c0 >> 1) + sg * 4);
        }
        asm volatile("cp.async.commit_group;");
    };

    issue_chunk(0);
    issue_chunk(1);

    int g = lane >> 2, t4 = lane & 3;
    for (int ic = 0; ic < 16; ic++) {
        int buf = ic & 1;
        if (ic < 15) asm volatile("cp.async.wait_group 1;");
        else         asm volatile("cp.async.wait_group 0;");
        __syncthreads();

        {
            const float* Asrc = Af32 + buf * (32 * 128);
#pragma unroll
            for (int kp = 0; kp < 8; kp++) {
                int k = (half * 8 + kp) * 2;
                float v0 = Asrc[k * 128 + px];
                float v1 = Asrc[(k + 1) * 128 + px];
                mynrm += v0 * v0 + v1 * v1;
                As32[px * 20 + half * 8 + kp] = pack_bf2(v0, v1);
            }
        }
        __syncthreads();

        {
            const unsigned* Ws = Wst + buf * (128 * 20);
#pragma unroll
            for (int k16 = 0; k16 < 2; k16++) {
                unsigned a[2][4];
#pragma unroll
                for (int mt = 0; mt < 2; mt++) {
                    int row = wm * 32 + mt * 16 + g;
                    int base = row * 20 + k16 * 8 + t4;
                    a[mt][0] = As32[base];
                    a[mt][1] = As32[base + 8 * 20];
                    a[mt][2] = As32[base + 4];
                    a[mt][3] = As32[base + 8 * 20 + 4];
                }
#pragma unroll
                for (int nt = 0; nt < 8; nt++) {
                    int pr = wn * 64 + nt * 8 + g;
                    int bb = pr * 20 + k16 * 8 + t4;
                    unsigned b0 = Ws[bb], b1 = Ws[bb + 4];
#pragma unroll
                    for (int mt = 0; mt < 2; mt++) mma16816(acc[mt][nt], a[mt], b0, b1);
                }
            }
        }
        __syncthreads();
        if (ic + 2 < 16) issue_chunk(ic + 2);
    }

    atomicAdd(&normsh[px], mynrm);
    __syncthreads();

#pragma unroll
    for (int mt = 0; mt < 2; mt++) {
#pragma unroll
        for (int h = 0; h < 2; h++) {
            float m = -1e30f;
#pragma unroll
            for (int nt = 0; nt < 8; nt++)
                m = fmaxf(m, fmaxf(acc[mt][nt][h * 2], acc[mt][nt][h * 2 + 1]));
            m = fmaxf(m, __shfl_xor_sync(0xFFFFFFFFu, m, 1));
            m = fmaxf(m, __shfl_xor_sync(0xFFFFFFFFu, m, 2));
            if ((lane & 3) == 0) {
                int p = wm * 32 + mt * 16 + h * 8 + g;
                float inv = 1.0f / fmaxf(sqrtf(normsh[p]), 1e-8f);
                float sim = m * inv;
                float mv = fminf(fmaxf(M[gpix0 + p], 0.f), 1.f);
                float d = 1.0f - sim;
                g_score[wn][gpix0 + p] = (wn == 0) ? d * mv : d * (1.0f - mv);
            }
        }
    }
}

// ---------------- kernel 3: candidate selection (persistent, 128 blocks) ----------------
#define SELB 128u
__global__ __launch_bounds__(256) void select_cand() {
    int tid = threadIdx.x;
    int gid = blockIdx.x * 256 + tid;   // 32768 threads

    // phase 1: hist16 over both sides
    for (int i = gid; i < 2 * NP; i += 32768) {
        int side = (i >= NP);
        int e = i - side * NP;
        unsigned key = mapf(g_score[side][e]);
        atomicAdd(&g_hist16[side][key >> 16], 1u);
    }
    grid_barrier(SELB);

    // phase 2: pick16 (blocks 0,1)
    if (blockIdx.x < 2) {
        int side = blockIdx.x;
        __shared__ unsigned ps[256];
        unsigned s = 0;
        for (int b = tid * 256; b < tid * 256 + 256; b++) s += g_hist16[side][b];
        ps[tid] = s;
        __syncthreads();
        if (tid == 0) {
            unsigned cum = 0;
            int seg = 255;
            for (; seg >= 0; seg--) {
                if (cum + ps[seg] >= (unsigned)NCAND) break;
                cum += ps[seg];
            }
            int b;
            for (b = seg * 256 + 255; b > seg * 256; b--) {
                unsigned h = g_hist16[side][b];
                if (cum + h >= (unsigned)NCAND) break;
                cum += h;
            }
            g_thr16[side] = b;
            g_rem[side] = NCAND - (int)cum;
        }
    }
    grid_barrier(SELB);

    // phase 3: hist8
    int thr16_0 = g_thr16[0], thr16_1 = g_thr16[1];
    for (int i = gid; i < 2 * NP; i += 32768) {
        int side = (i >= NP);
        int e = i - side * NP;
        unsigned key = mapf(g_score[side][e]);
        if ((int)(key >> 16) == (side ? thr16_1 : thr16_0))
            atomicAdd(&g_hist8[side][(key >> 8) & 255], 1u);
    }
    grid_barrier(SELB);

    // phase 4: pick8 (blocks 0,1)
    if (blockIdx.x < 2 && tid == 0) {
        int side = blockIdx.x;
        int rem = g_rem[side];
        unsigned cum = 0;
        int b;
        for (b = 255; b > 0; b--) {
            unsigned h = g_hist8[side][b];
            if (cum + h >= (unsigned)rem) break;
            cum += h;
        }
        g_thr24[side] = (((unsigned)g_thr16[side]) << 8) | (unsigned)b;
    }
    grid_barrier(SELB);

    // phase 5: collect
    unsigned t24_0 = g_thr24[0], t24_1 = g_thr24[1];
    for (int i = gid; i < 2 * NP; i += 32768) {
        int side = (i >= NP);
        int e = i - side * NP;
        unsigned key24 = mapf(g_score[side][e]) >> 8;
        if (key24 >= (side ? t24_1 : t24_0)) {
            int pos = atomicAdd(&g_ccnt[side], 1);
            if (pos < CAP) g_cand[side][pos] = e;
        }
    }
}

// ---------------- kernel 4: exact FP32 rescore (8 candidates per block) ----------------
__global__ __launch_bounds__(256) void rescore_kernel(
    const float* __restrict__ F, const float* __restrict__ M) {
    int side = blockIdx.y;
    int s0 = blockIdx.x * 8;
    int tid = threadIdx.x, lane = tid & 31, q = tid >> 5;
    int cnt = min(g_ccnt[side], CAP);

    __shared__ float fsh[8][CDIM];
    __shared__ float nrm[8];

    int s = s0 + q;
    bool valid = (s < cnt);
    int idx = g_cand[side][valid ? s : 0];
    int n = idx / HW, hw = idx - n * HW;
    const float* base = F + (size_t)n * CDIM * HW + hw;

    float partial = 0.f;
#pragma unroll
    for (int i = 0; i < 16; i++) {
        int c = lane + 32 * i;
        float v = base[(size_t)c * HW];
        fsh[q][c] = v;
        partial += v * v;
    }
#pragma unroll
    for (int o = 16; o > 0; o >>= 1) partial += __shfl_xor_sync(0xFFFFFFFFu, partial, o);
    if (lane == 0) nrm[q] = partial;
    __syncthreads();

    const float* Wb = g_Wt + side * 64 + lane * 2;
    float d0 = 0.f, d1 = 0.f;
#pragma unroll 4
    for (int c = 0; c < CDIM; c++) {
        float f = fsh[q][c];
        float2 wv = *(const float2*)(Wb + (size_t)c * 128);
        d0 = fmaf(f, wv.x, d0);
        d1 = fmaf(f, wv.y, d1);
    }
    float m = fmaxf(d0, d1);
#pragma unroll
    for (int o = 16; o > 0; o >>= 1) m = fmaxf(m, __shfl_xor_sync(0xFFFFFFFFu, m, o));
    if (lane == 0) {
        float val = -3.0e38f;
        if (valid) {
            float inv = 1.0f / fmaxf(sqrtf(nrm[q]), 1e-8f);
            float sim = m * inv;
            float mv = fminf(fmaxf(M[idx], 0.f), 1.f);
            val = (side == 0) ? (1.0f - sim) * mv : (1.0f - sim) * (1.0f - mv);
        }
        g_cscore[side][s] = val;
    }
}

// ---------------- kernel 5: exact top-256 among candidates ----------------
__global__ void select256_kernel() {
    int side = blockIdx.x, tid = threadIdx.x;
    const float* sc = g_cscore[side];
    const int* cd = g_cand[side];
    __shared__ unsigned hist[256];
    __shared__ unsigned sh_pfx, sh_dmask;
    __shared__ int sh_krem, gcnt, tcnt;
    __shared__ int glist[NSEL];
    __shared__ int ties[CAP];

    if (tid == 0) { sh_pfx = 0; sh_dmask = 0; sh_krem = NSEL; }
    __syncthreads();
    for (int shift = 24; shift >= 0; shift -= 8) {
        if (tid < 256) hist[tid] = 0;
        __syncthreads();
        unsigned dm = sh_dmask, pf = sh_pfx;
        for (int i = tid; i < CAP; i += blockDim.x) {
            unsigned key = mapf(sc[i]);
            if ((key & dm) == pf) atomicAdd(&hist[(key >> shift) & 255], 1u);
        }
        __syncthreads();
        if (tid == 0) {
            int kr = sh_krem;
            unsigned cum = 0;
            int d = 255;
            for (; d > 0; d--) {
                if (cum + hist[d] >= (unsigned)kr) break;
                cum += hist[d];
            }
            sh_krem  = kr - (int)cum;
            sh_pfx   = sh_pfx | ((unsigned)d << shift);
            sh_dmask = sh_dmask | (0xFFu << shift);
        }
        __syncthreads();
    }
    if (tid == 0) { gcnt = 0; tcnt = 0; }
    __syncthreads();
    unsigned thr = sh_pfx;
    for (int i = tid; i < CAP; i += blockDim.x) {
        unsigned key = mapf(sc[i]);
        if (key > thr) {
            int p = atomicAdd(&gcnt, 1);
            if (p < NSEL) glist[p] = cd[i];
        } else if (key == thr) {
            int p = atomicAdd(&tcnt, 1);
            if (p < CAP) ties[p] = cd[i];
        }
    }
    __syncthreads();
    int G = min(gcnt, NSEL);
    for (int e = tid; e < G; e += blockDim.x) {
        int pe = glist[e], r = 0;
        for (int j = 0; j < G; j++) r += (glist[j] < pe);
        g_idx[side][r] = pe;
    }
    int need = NSEL - G;
    int T = min(tcnt, CAP);
    for (int e = tid; e < T; e += blockDim.x) {
        int pe = ties[e], r = 0;
        for (int j = 0; j < T; j++) r += (ties[j] < pe);
        if (r < need) g_idx[side][G + r] = pe;
    }
}

// ---------------- kernel 6: fused gather + refine + loss + outputs (64 blocks) ----------------
#define RFB 64u
__global__ __launch_bounds__(256) void refine_all(
    const float* __restrict__ F,
    const float* __restrict__ fg, const float* __restrict__ bg,
    float* __restrict__ out) {
    __shared__ float sh[8 * CDIM + 8 * KP];   // 18.5 KB, reused per phase
    int tid = threadIdx.x, b = blockIdx.x;

    // ---- phase 0: gather 8 samples + proto init copy ----
    for (int l = 0; l < 8; l++) {
        int t = b * 8 + l;
        int side = t >> 8, s = t & 255;
        int idx = g_idx[side][s];
        int n = idx / HW, hw = idx - n * HW;
        const float* base = F + (size_t)n * CDIM * HW + hw;
        float v0 = base[(size_t)tid * HW];
        float v1 = base[(size_t)(tid + 256) * HW];
        float ss = v0 * v0 + v1 * v1;
#pragma unroll
        for (int o = 16; o > 0; o >>= 1) ss += __shfl_xor_sync(0xFFFFFFFFu, ss, o);
        if ((tid & 31) == 0) sh[tid >> 5] = ss;
        __syncthreads();
        float tot = sh[0] + sh[1] + sh[2] + sh[3] + sh[4] + sh[5] + sh[6] + sh[7];
        float inv = 1.0f / fmaxf(sqrtf(tot), 1e-8f);
        g_feats[side][s * CDIM + tid]       = v0 * inv;
        g_feats[side][s * CDIM + tid + 256] = v1 * inv;
        __syncthreads();
    }
    {
        int base = b * 1024;
#pragma unroll
        for (int i = 0; i < 4; i++) {
            int fl = base + tid + 256 * i;
            float v = (fl < 32768) ? fg[fl] : bg[fl - 32768];
            (&g_p[0][0])[fl] = v;
        }
    }
    grid_barrier(RFB);

    // ---- refinement loop ----
    int side_a = b >> 5, bpos = b & 31;
    for (int it = 0; it < NREF; it++) {
        float step = 0.1f / (1.0f + 0.5f * (float)it);

        // assign: 8 samples (s0..s0+7) on side_a
        {
            float* fsm = sh;                 // 8*512
            float* dsm = sh + 8 * CDIM;      // 8*64
            int s0 = bpos * 8;
            const float4* src = (const float4*)(g_feats[side_a] + s0 * CDIM);
#pragma unroll
            for (int i = 0; i < 4; i++)
                ((float4*)fsm)[tid + 256 * i] = src[tid + 256 * i];
            __syncthreads();
            int j = tid & 63, sg = tid >> 6;
            const float* pj = g_p[side_a] + j * CDIM;
            const float* fa = fsm + (sg * 2) * CDIM;
            const float* fb = fa + CDIM;
            float d0 = 0.f, d1 = 0.f;
            for (int c = 0; c < CDIM; c += 4) {
                float4 pv = *(const float4*)(pj + c);
                float4 av = *(const float4*)(fa + c);
                float4 bv = *(const float4*)(fb + c);
                d0 = fmaf(av.x, pv.x, fmaf(av.y, pv.y, fmaf(av.z, pv.z, fmaf(av.w, pv.w, d0))));
                d1 = fmaf(bv.x, pv.x, fmaf(bv.y, pv.y, fmaf(bv.z, pv.z, fmaf(bv.w, pv.w, d1))));
            }
            dsm[(sg * 2) * KP + j] = d0;
            dsm[(sg * 2 + 1) * KP + j] = d1;
            __syncthreads();
            if (tid < 8) {
                float best = dsm[tid * KP];
                int bj = 0;
                for (int jj = 1; jj < KP; jj++) {
                    float v = dsm[tid * KP + jj];
                    if (v > best) { best = v; bj = jj; }
                }
                g_assign[side_a][s0 + tid] = bj;
            }
        }
        grid_barrier(RFB);

        // update: 2 cluster tasks per block
        for (int jj = 0; jj < 2; jj++) {
            int t2 = b * 2 + jj;
            int side = t2 >> 6, k = t2 & 63;
            int* asg = (int*)sh;          // 256
            float* red = sh + 256;        // 256
            asg[tid] = g_assign[side][tid];
            __syncthreads();
            float s0f = 0.f, s1f = 0.f;
            int cnt = 0;
            for (int s = 0; s < NSEL; s++) {
                if (asg[s] == k) {
                    cnt++;
                    const float* f = g_feats[side] + s * CDIM;
                    s0f += f[tid];
                    s1f += f[tid + 256];
                }
            }
            float denom = fmaxf((float)cnt, 1.0f);
            float p0 = g_p[side][k * CDIM + tid];
            float p1 = g_p[side][k * CDIM + tid + 256];
            float v0 = (1.0f - step) * p0 + step * (s0f / denom);
            float v1 = (1.0f - step) * p1 + step * (s1f / denom);
            red[tid] = v0 * v0 + v1 * v1;
            __syncthreads();
            for (int o = 128; o > 0; o >>= 1) {
                if (tid < o) red[tid] += red[tid + o];
                __syncthreads();
            }
            float inv = 1.0f / fmaxf(sqrtf(red[0]), 1e-8f);
            if (cnt > 0) {
                g_p[side][k * CDIM + tid]       = v0 * inv;
                g_p[side][k * CDIM + tid + 256] = v1 * inv;
            }
            __syncthreads();
        }
        grid_barrier(RFB);
    }

    // ---- loss: 4 samples per block ----
    for (int l = 0; l < 4; l++) {
        int s = b * 4 + l;
        float* posf = sh;            // 512
        float* negf = sh + 512;      // 512
        float* dsm  = sh + 1024;     // 192
        posf[tid]       = g_feats[0][s * CDIM + tid];
        posf[tid + 256] = g_feats[0][s * CDIM + tid + 256];
        negf[tid]       = g_feats[1][s * CDIM + tid];
        negf[tid + 256] = g_feats[1][s * CDIM + tid + 256];
        __syncthreads();
        if (tid < 192) {
            int kind = tid / 64, j = tid % 64;
            const float* f = (kind == 2) ? negf : posf;
            const float* p = ((kind == 1) ? g_p[1] : g_p[0]) + j * CDIM;
            float d = 0.f;
            for (int c = 0; c < CDIM; c += 4) {
                float4 pv = *(const float4*)(p + c);
                d = fmaf(f[c], pv.x, fmaf(f[c+1], pv.y, fmaf(f[c+2], pv.z, fmaf(f[c+3], pv.w, d))));
            }
            dsm[tid] = d;
        }
        __syncthreads();
        if (tid == 0) {
            float mp = dsm[0];
            for (int j = 1; j < 64; j++) mp = fmaxf(mp, dsm[j]);
            float mb = dsm[64];
            for (int j = 65; j < 128; j++) mb = fmaxf(mb, dsm[j]);
            float mn = dsm[128];
            for (int j = 129; j < 192; j++) mn = fmaxf(mn, dsm[j]);
            g_simpos[s] = mp;
            g_simneg[s] = mn;
            float a1 = mp / TAU;
            float sum1 = 0.f;
            for (int j = 0; j < 64; j++) sum1 += expf(dsm[j] / TAU - a1);
            float aall = fmaxf(mp, mb) / TAU;
            float sum2 = 0.f;
            for (int j = 0; j < 128; j++) sum2 += expf(dsm[j] / TAU - aall);
            g_info[s] = (aall + logf(sum2)) - (a1 + logf(sum1));
        }
        __syncthreads();
    }

    // ---- refined output: 2 proto rows per block ----
    for (int jj = 0; jj < 2; jj++) {
        int r = b * 2 + jj;
        int side = r >> 6, k = r & 63;
        const float* src = side ? bg : fg;
        float v0 = (1.0f - MBLEND) * src[k * CDIM + tid]       + MBLEND * g_p[side][k * CDIM + tid];
        float v1 = (1.0f - MBLEND) * src[k * CDIM + tid + 256] + MBLEND * g_p[side][k * CDIM + tid + 256];
        float* red = sh;
        red[tid] = v0 * v0 + v1 * v1;
        __syncthreads();
        for (int o = 128; o > 0; o >>= 1) {
            if (tid < o) red[tid] += red[tid + o];
            __syncthreads();
        }
        float inv = 1.0f / fmaxf(sqrtf(red[0]), 1e-8f);
        out[1 + side * (KP * CDIM) + k * CDIM + tid]       = v0 * inv;
        out[1 + side * (KP * CDIM) + k * CDIM + tid + 256] = v1 * inv;
        __syncthreads();
    }
    grid_barrier(RFB);

    // ---- finalize (block 0) ----
    if (b == 0) {
        float* r1 = sh;
        float* r2 = sh + 256;
        float* r3 = sh + 512;
        r1[tid] = g_simpos[tid];
        r2[tid] = g_simneg[tid];
        r3[tid] = g_info[tid];
        __syncthreads();
        for (int o = 128; o > 0; o >>= 1) {
            if (tid < o) { r1[tid] += r1[tid+o]; r2[tid] += r2[tid+o]; r3[tid] += r3[tid+o]; }
            __syncthreads();
        }
        if (tid == 0) {
            float mp = r1[0] / (float)NSEL;
            float mn = r2[0] / (float)NSEL;
            float mi = r3[0] / (float)NSEL;
            out[0] = fmaxf(0.f, MARGIN + mn - mp) + 0.25f * mi;
        }
    }
}

// ---------------- launch ----------------
extern "C" void kernel_launch(void* const* d_in, const int* in_sizes, int n_in,
                              void* d_out, int out_size) {
    const float* fg = (const float*)d_in[0];
    const float* bg = (const float*)d_in[1];
    const float* F  = (const float*)d_in[2];
    const float* M  = (const float*)d_in[3];
    float* out = (float*)d_out;

    cudaFuncSetAttribute(score_tc, cudaFuncAttributeMaxDynamicSharedMemorySize, SCORE_SMEM);

    prep_all<<<256, 256>>>(fg, bg);
    score_tc<<<NP / 128, 256, SCORE_SMEM>>>(F, M);
    select_cand<<<SELB, 256>>>();
    rescore_kernel<<<dim3(CAP / 8, 2), 256>>>(F, M);
    select256_kernel<<<2, 256>>>();
    refine_all<<<RFB, 256>>>(F, fg, bg, out);
}

// round 13
// speedup vs baseline: 1.1403x; 1.1403x over previous
#include <cuda_runtime.h>
#include <cuda_bf16.h>
#include <math.h>

#define NP      147456      // 16*96*96
#define HW      9216        // 96*96
#define CDIM    512
#define KP      64          // protos per side
#define NSEL    256
#define NREF    10
#define TAU     0.07f
#define MARGIN  0.2f
#define MBLEND  0.3f

#define NCAND   3072        // approx-candidate target per side
#define CAP     4096        // candidate buffer cap

// ---------------- scratch ----------------
__device__ float    g_Wt[CDIM * 128];         // [c][j] fp32 transposed protos (rescore)
__device__ unsigned g_Wb16u[128 * 256];       // [proto][ch-pair] bf16x2 protos
__device__ float    g_score[2][NP];           // approx scores (bf16 MMA)
__device__ unsigned g_hist16[2][65536];
__device__ unsigned g_hist8[2][256];
__device__ int      g_thr16[2];
__device__ int      g_rem[2];
__device__ unsigned g_thr24[2];
__device__ int      g_ccnt[2];
__device__ int      g_cand[2][CAP];
__device__ float    g_cscore[2][CAP];
__device__ int      g_idx[2][NSEL];
__device__ float    g_feats[2][NSEL * CDIM];
__device__ float    g_p[2][KP * CDIM];
__device__ int      g_assign[2][NSEL];
__device__ float    g_simpos[NSEL], g_simneg[NSEL], g_info[NSEL];

// ---------------- grid barrier (persistent; 128 blocks << 148 SMs) ----------------
__device__ unsigned g_barcnt = 0;
__device__ volatile unsigned g_bargen = 0;
__device__ __forceinline__ void grid_barrier(unsigned nblk) {
    __syncthreads();
    if (threadIdx.x == 0) {
        __threadfence();
        unsigned gen = g_bargen;
        if (atomicAdd(&g_barcnt, 1u) == nblk - 1u) {
            atomicExch(&g_barcnt, 0u);
            __threadfence();
            g_bargen = gen + 1u;
        } else {
            while (g_bargen == gen) { }
            __threadfence();
        }
    }
    __syncthreads();
}

// ---------------- helpers ----------------
__device__ __forceinline__ unsigned mapf(float x) {
    unsigned u = __float_as_uint(x);
    return (u & 0x80000000u) ? ~u : (u | 0x80000000u);
}
__device__ __forceinline__ unsigned pack_bf2(float lo, float hi) {
    unsigned r;
    asm("cvt.rn.bf16x2.f32 %0, %1, %2;" : "=r"(r) : "f"(hi), "f"(lo));
    return r;
}
__device__ __forceinline__ void mma16816(float* c, const unsigned* a, unsigned b0, unsigned b1) {
    asm volatile("mma.sync.aligned.m16n8k16.row.col.f32.bf16.bf16.f32 "
                 "{%0,%1,%2,%3}, {%4,%5,%6,%7}, {%8,%9}, {%0,%1,%2,%3};"
                 : "+f"(c[0]), "+f"(c[1]), "+f"(c[2]), "+f"(c[3])
                 : "r"(a[0]), "r"(a[1]), "r"(a[2]), "r"(a[3]), "r"(b0), "r"(b1));
}
__device__ __forceinline__ unsigned sptr(const void* p) {
    return (unsigned)__cvta_generic_to_shared(p);
}
__device__ __forceinline__ void cp16_cg(unsigned s, const void* g) {
    asm volatile("cp.async.cg.shared.global [%0], [%1], 16;" :: "r"(s), "l"(g));
}
__device__ __forceinline__ void cp16_ca(unsigned s, const void* g) {
    asm volatile("cp.async.ca.shared.global [%0], [%1], 16;" :: "r"(s), "l"(g));
}

// ---------------- prep ----------------
__global__ void prep_wt(const float* __restrict__ fg, const float* __restrict__ bg) {
    int j = blockIdx.x, c = threadIdx.x;
    float v = (j < KP) ? fg[j * CDIM + c] : bg[(j - KP) * CDIM + c];
    g_Wt[c * 128 + j] = v;
}
__global__ void prep_wb16(const float* __restrict__ fg, const float* __restrict__ bg) {
    int j = blockIdx.x, t = threadIdx.x;  // 128 threads
    const float* src = (j < KP) ? (fg + j * CDIM) : (bg + (j - KP) * CDIM);
    int c = t * 4;
    g_Wb16u[j * 256 + t * 2]     = pack_bf2(src[c],     src[c + 1]);
    g_Wb16u[j * 256 + t * 2 + 1] = pack_bf2(src[c + 2], src[c + 3]);
}
__global__ void zero_aux() {
    int t = blockIdx.x * blockDim.x + threadIdx.x;
    unsigned* h16 = &g_hist16[0][0];
    for (int i = t; i < 2 * 65536; i += gridDim.x * blockDim.x) h16[i] = 0;
    if (t < 512) (&g_hist8[0][0])[t] = 0;
    if (t < 2) g_ccnt[t] = 0;
}

// ---------------- approx score: bf16 TC GEMM, cp.async double-buffered ----------------
#define SCORE_SMEM (32768 + 20480 + 10240 + 512)
__global__ __launch_bounds__(256, 2) void score_tc(
    const float* __restrict__ F, const float* __restrict__ M) {
    extern __shared__ char smem_raw[];
    float*    Af32   = (float*)smem_raw;
    unsigned* Wst    = (unsigned*)(smem_raw + 32768);
    unsigned* As32   = (unsigned*)(smem_raw + 32768 + 20480);
    float*    normsh = (float*)(smem_raw + 63488);

    int tid = threadIdx.x, lane = tid & 31, w = tid >> 5;
    int wm = w >> 1, wn = w & 1;
    int gpix0 = blockIdx.x * 128;
    int n = gpix0 / HW, hw0 = gpix0 - n * HW;
    const float* Fb = F + (size_t)n * CDIM * HW + hw0;

    if (tid < 128) normsh[tid] = 0.f;

    float acc[2][8][4];
#pragma unroll
    for (int a = 0; a < 2; a++)
#pragma unroll
        for (int b = 0; b < 8; b++)
#pragma unroll
            for (int d = 0; d < 4; d++) acc[a][b][d] = 0.f;

    int px = tid & 127, half = tid >> 7;
    float mynrm = 0.f;

    auto issue_chunk = [&](int ic) {
        int buf = ic & 1;
        int c0 = ic * 32;
        float* Ad = Af32 + buf * (32 * 128);
#pragma unroll
        for (int j = 0; j < 4; j++) {
            int idx = tid + 256 * j;
            int r = idx >> 5, sg = idx & 31;
            cp16_cg(sptr(Ad + r * 128 + sg * 4),
                    Fb + (size_t)(c0 + r) * HW + sg * 4);
        }
        unsigned* Wd = Wst + buf * (128 * 20);
#pragma unroll
        for (int j = 0; j < 2; j++) {
            int idx = tid + 256 * j;
            int p = idx >> 2, sg = idx & 3;
            cp16_ca(sptr(Wd + p * 20 + sg * 4),
                    g_Wb16u + p * 256 + (c0 >> 1) + sg * 4);
        }
        asm volatile("cp.async.commit_group;");
    };

    issue_chunk(0);
    issue_chunk(1);

    int g = lane >> 2, t4 = lane & 3;
    for (int ic = 0; ic < 16; ic++) {
        int buf = ic & 1;
        if (ic < 15) asm volatile("cp.async.wait_group 1;");
        else         asm volatile("cp.async.wait_group 0;");
        __syncthreads();

        {
            const float* Asrc = Af32 + buf * (32 * 128);
#pragma unroll
            for (int kp = 0; kp < 8; kp++) {
                int k = (half * 8 + kp) * 2;
                float v0 = Asrc[k * 128 + px];
                float v1 = Asrc[(k + 1) * 128 + px];
                mynrm += v0 * v0 + v1 * v1;
                As32[px * 20 + half * 8 + kp] = pack_bf2(v0, v1);
            }
        }
        __syncthreads();

        {
            const unsigned* Ws = Wst + buf * (128 * 20);
#pragma unroll
            for (int k16 = 0; k16 < 2; k16++) {
                unsigned a[2][4];
#pragma unroll
                for (int mt = 0; mt < 2; mt++) {
                    int row = wm * 32 + mt * 16 + g;
                    int base = row * 20 + k16 * 8 + t4;
                    a[mt][0] = As32[base];
                    a[mt][1] = As32[base + 8 * 20];
                    a[mt][2] = As32[base + 4];
                    a[mt][3] = As32[base + 8 * 20 + 4];
                }
#pragma unroll
                for (int nt = 0; nt < 8; nt++) {
                    int pr = wn * 64 + nt * 8 + g;
                    int bb = pr * 20 + k16 * 8 + t4;
                    unsigned b0 = Ws[bb], b1 = Ws[bb + 4];
#pragma unroll
                    for (int mt = 0; mt < 2; mt++) mma16816(acc[mt][nt], a[mt], b0, b1);
                }
            }
        }
        __syncthreads();
        if (ic + 2 < 16) issue_chunk(ic + 2);
    }

    atomicAdd(&normsh[px], mynrm);
    __syncthreads();

#pragma unroll
    for (int mt = 0; mt < 2; mt++) {
#pragma unroll
        for (int h = 0; h < 2; h++) {
            float m = -1e30f;
#pragma unroll
            for (int nt = 0; nt < 8; nt++)
                m = fmaxf(m, fmaxf(acc[mt][nt][h * 2], acc[mt][nt][h * 2 + 1]));
            m = fmaxf(m, __shfl_xor_sync(0xFFFFFFFFu, m, 1));
            m = fmaxf(m, __shfl_xor_sync(0xFFFFFFFFu, m, 2));
            if ((lane & 3) == 0) {
                int p = wm * 32 + mt * 16 + h * 8 + g;
                float inv = 1.0f / fmaxf(sqrtf(normsh[p]), 1e-8f);
                float sim = m * inv;
                float mv = fminf(fmaxf(M[gpix0 + p], 0.f), 1.f);
                float d = 1.0f - sim;
                g_score[wn][gpix0 + p] = (wn == 0) ? d * mv : d * (1.0f - mv);
            }
        }
    }
}

// ---------------- candidate selection (grid-parallel, R11 layout) ----------------
__global__ void hist16_kernel() {
    int side = blockIdx.y;
    int i = blockIdx.x * 256 + threadIdx.x;
    unsigned key = mapf(g_score[side][i]);
    atomicAdd(&g_hist16[side][key >> 16], 1u);
}

__global__ void pick16_kernel() {
    int side = blockIdx.x, tid = threadIdx.x;
    __shared__ unsigned ps[256];
    unsigned s = 0;
    for (int b = tid * 256; b < tid * 256 + 256; b++) s += g_hist16[side][b];
    ps[tid] = s;
    __syncthreads();
    if (tid == 0) {
        unsigned cum = 0;
        int seg = 255;
        for (; seg >= 0; seg--) {
            if (cum + ps[seg] >= (unsigned)NCAND) break;
            cum += ps[seg];
        }
        int b;
        for (b = seg * 256 + 255; b > seg * 256; b--) {
            unsigned h = g_hist16[side][b];
            if (cum + h >= (unsigned)NCAND) break;
            cum += h;
        }
        g_thr16[side] = b;
        g_rem[side] = NCAND - (int)cum;
    }
}

__global__ void hist8_kernel() {
    int side = blockIdx.y;
    int i = blockIdx.x * 256 + threadIdx.x;
    unsigned key = mapf(g_score[side][i]);
    if ((int)(key >> 16) == g_thr16[side])
        atomicAdd(&g_hist8[side][(key >> 8) & 255], 1u);
}

__global__ void pick8_kernel() {
    int side = blockIdx.x;
    if (threadIdx.x == 0) {
        int rem = g_rem[side];
        unsigned cum = 0;
        int b;
        for (b = 255; b > 0; b--) {
            unsigned h = g_hist8[side][b];
            if (cum + h >= (unsigned)rem) break;
            cum += h;
        }
        g_thr24[side] = (((unsigned)g_thr16[side]) << 8) | (unsigned)b;
    }
}

__global__ void collect_kernel() {
    int side = blockIdx.y;
    int i = blockIdx.x * 256 + threadIdx.x;
    unsigned key24 = mapf(g_score[side][i]) >> 8;
    if (key24 >= g_thr24[side]) {
        int pos = atomicAdd(&g_ccnt[side], 1);
        if (pos < CAP) g_cand[side][pos] = i;
    }
}

// ---------------- exact FP32 rescore v3: 16 candidates per block ----------------
// half-warp per candidate in the dot phase; float4 Wt loads (4 protos per lane)
__global__ __launch_bounds__(256) void rescore_kernel(
    const float* __restrict__ F, const float* __restrict__ M) {
    int side = blockIdx.y;
    int s0 = blockIdx.x * 16;
    int tid = threadIdx.x, lane = tid & 31, w = tid >> 5;
    int cnt = min(g_ccnt[side], CAP);

    if (s0 >= cnt) {                 // pure padding block: sentinels, no work
        if (tid < 16) g_cscore[side][s0 + tid] = -3.0e38f;
        return;
    }

    __shared__ float fsh[16][CDIM];  // 32 KB
    __shared__ float nrm[16];

    // load phase: warp w loads candidates 2w, 2w+1 (full warp each)
#pragma unroll
    for (int h = 0; h < 2; h++) {
        int cslot = 2 * w + h;
        int s = s0 + cslot;
        bool valid = (s < cnt);
        int idx = g_cand[side][valid ? s : 0];
        int n = idx / HW, hw = idx - n * HW;
        const float* base = F + (size_t)n * CDIM * HW + hw;
        float partial = 0.f;
#pragma unroll
        for (int i = 0; i < 16; i++) {
            int c = lane + 32 * i;
            float v = base[(size_t)c * HW];
            fsh[cslot][c] = v;
            partial += v * v;
        }
#pragma unroll
        for (int o = 16; o > 0; o >>= 1)
            partial += __shfl_xor_sync(0xFFFFFFFFu, partial, o);
        if (lane == 0) nrm[cslot] = partial;
    }
    __syncthreads();

    // dot phase: half-warp per candidate, 4 protos per lane via float4
    int half = lane >> 4, l16 = lane & 15;
    int cslot = 2 * w + half;
    const float* Wb = g_Wt + side * 64 + l16 * 4;
    float d0 = 0.f, d1 = 0.f, d2 = 0.f, d3 = 0.f;
#pragma unroll 4
    for (int c = 0; c < CDIM; c++) {
        float f = fsh[cslot][c];
        float4 wv = *(const float4*)(Wb + (size_t)c * 128);
        d0 = fmaf(f, wv.x, d0);
        d1 = fmaf(f, wv.y, d1);
        d2 = fmaf(f, wv.z, d2);
        d3 = fmaf(f, wv.w, d3);
    }
    float m = fmaxf(fmaxf(d0, d1), fmaxf(d2, d3));
#pragma unroll
    for (int o = 8; o > 0; o >>= 1)
        m = fmaxf(m, __shfl_xor_sync(0xFFFFFFFFu, m, o));   // stays within 16-lane group
    if (l16 == 0) {
        int s = s0 + cslot;
        bool valid = (s < cnt);
        float val = -3.0e38f;
        if (valid) {
            int idx = g_cand[side][s];
            float inv = 1.0f / fmaxf(sqrtf(nrm[cslot]), 1e-8f);
            float sim = m * inv;
            float mv = fminf(fmaxf(M[idx], 0.f), 1.f);
            val = (side == 0) ? (1.0f - sim) * mv : (1.0f - sim) * (1.0f - mv);
        }
        g_cscore[side][s] = val;
    }
}

// ---------------- exact top-256 among candidates ----------------
__global__ void select256_kernel() {
    int side = blockIdx.x, tid = threadIdx.x;
    const float* sc = g_cscore[side];
    const int* cd = g_cand[side];
    __shared__ unsigned hist[256];
    __shared__ unsigned sh_pfx, sh_dmask;
    __shared__ int sh_krem, gcnt, tcnt;
    __shared__ int glist[NSEL];
    __shared__ int ties[CAP];

    if (tid == 0) { sh_pfx = 0; sh_dmask = 0; sh_krem = NSEL; }
    __syncthreads();
    for (int shift = 24; shift >= 0; shift -= 8) {
        if (tid < 256) hist[tid] = 0;
        __syncthreads();
        unsigned dm = sh_dmask, pf = sh_pfx;
        for (int i = tid; i < CAP; i += blockDim.x) {
            unsigned key = mapf(sc[i]);
            if ((key & dm) == pf) atomicAdd(&hist[(key >> shift) & 255], 1u);
        }
        __syncthreads();
        if (tid == 0) {
            int kr = sh_krem;
            unsigned cum = 0;
            int d = 255;
            for (; d > 0; d--) {
                if (cum + hist[d] >= (unsigned)kr) break;
                cum += hist[d];
            }
            sh_krem  = kr - (int)cum;
            sh_pfx   = sh_pfx | ((unsigned)d << shift);
            sh_dmask = sh_dmask | (0xFFu << shift);
        }
        __syncthreads();
    }
    if (tid == 0) { gcnt = 0; tcnt = 0; }
    __syncthreads();
    unsigned thr = sh_pfx;
    for (int i = tid; i < CAP; i += blockDim.x) {
        unsigned key = mapf(sc[i]);
        if (key > thr) {
            int p = atomicAdd(&gcnt, 1);
            if (p < NSEL) glist[p] = cd[i];
        } else if (key == thr) {
            int p = atomicAdd(&tcnt, 1);
            if (p < CAP) ties[p] = cd[i];
        }
    }
    __syncthreads();
    int G = min(gcnt, NSEL);
    for (int e = tid; e < G; e += blockDim.x) {
        int pe = glist[e], r = 0;
        for (int j = 0; j < G; j++) r += (glist[j] < pe);
        g_idx[side][r] = pe;
    }
    int need = NSEL - G;
    int T = min(tcnt, CAP);
    for (int e = tid; e < T; e += blockDim.x) {
        int pe = ties[e], r = 0;
        for (int j = 0; j < T; j++) r += (ties[j] < pe);
        if (r < need) g_idx[side][G + r] = pe;
    }
}

// ---------------- gather + normalize selected features ----------------
__global__ void gather_kernel(const float* __restrict__ F) {
    int s = blockIdx.x, side = blockIdx.y;
    int idx = g_idx[side][s];
    int n = idx / HW, hw = idx - n * HW;
    const float* base = F + (size_t)n * CDIM * HW + hw;
    int tid = threadIdx.x;  // 128
    float v[4], ss = 0.f;
#pragma unroll
    for (int i = 0; i < 4; i++) {
        int c = tid + i * 128;
        v[i] = base[(size_t)c * HW];
        ss += v[i] * v[i];
    }
#pragma unroll
    for (int o = 16; o > 0; o >>= 1) ss += __shfl_xor_sync(0xFFFFFFFFu, ss, o);
    __shared__ float wsum[4];
    if ((tid & 31) == 0) wsum[tid >> 5] = ss;
    __syncthreads();
    float inv = 1.0f / fmaxf(sqrtf(wsum[0] + wsum[1] + wsum[2] + wsum[3]), 1e-8f);
#pragma unroll
    for (int i = 0; i < 4; i++)
        g_feats[side][s * CDIM + tid + i * 128] = v[i] * inv;
}

__global__ void init_p(const float* __restrict__ fg, const float* __restrict__ bg) {
    int k = blockIdx.x, side = blockIdx.y, c = threadIdx.x;
    const float* src = side ? bg : fg;
    g_p[side][k * CDIM + c] = src[k * CDIM + c];
}

// ---------------- fused refinement iteration: assign (4 samples/blk) + update ----------------
// 128 blocks x 256 threads; one internal grid barrier
#define RFB 128u
__global__ __launch_bounds__(256) void refine_iter(float step) {
    int b = blockIdx.x, tid = threadIdx.x;
    __shared__ float sh[4 * CDIM + 4 * KP];   // fsm 4*512 | dsm 4*64  (9 KB)

    // ---- assign: side = b>>6, samples s0..s0+3 ----
    {
        float* fsm = sh;
        float* dsm = sh + 4 * CDIM;
        int side = b >> 6;
        int s0 = (b & 63) * 4;
        const float4* src = (const float4*)(g_feats[side] + s0 * CDIM);
#pragma unroll
        for (int i = 0; i < 2; i++)
            ((float4*)fsm)[tid + 256 * i] = src[tid + 256 * i];
        __syncthreads();
        int j = tid & 63, sg = tid >> 6;      // sg = sample 0..3
        const float* pj = g_p[side] + j * CDIM;
        const float* fa = fsm + sg * CDIM;
        float d0 = 0.f;
        for (int c = 0; c < CDIM; c += 4) {
            float4 pv = *(const float4*)(pj + c);
            float4 av = *(const float4*)(fa + c);
            d0 = fmaf(av.x, pv.x, fmaf(av.y, pv.y, fmaf(av.z, pv.z, fmaf(av.w, pv.w, d0))));
        }
        dsm[sg * KP + j] = d0;
        __syncthreads();
        if (tid < 4) {
            float best = dsm[tid * KP];
            int bj = 0;
            for (int jj = 1; jj < KP; jj++) {
                float v = dsm[tid * KP + jj];
                if (v > best) { best = v; bj = jj; }
            }
            g_assign[side][s0 + tid] = bj;
        }
    }
    grid_barrier(RFB);

    // ---- update: side = b>>6, cluster k = b&63 ----
    {
        int side = b >> 6, k = b & 63;
        int* asg = (int*)sh;           // 256 ints
        float* red = sh + 256;         // 256 floats
        asg[tid] = g_assign[side][tid];
        __syncthreads();
        float s0f = 0.f, s1f = 0.f;
        int cnt = 0;
        for (int s = 0; s < NSEL; s++) {
            if (asg[s] == k) {
                cnt++;
                const float* f = g_feats[side] + s * CDIM;
                s0f += f[tid];
                s1f += f[tid + 256];
            }
        }
        float denom = fmaxf((float)cnt, 1.0f);
        float p0 = g_p[side][k * CDIM + tid];
        float p1 = g_p[side][k * CDIM + tid + 256];
        float v0 = (1.0f - step) * p0 + step * (s0f / denom);
        float v1 = (1.0f - step) * p1 + step * (s1f / denom);
        red[tid] = v0 * v0 + v1 * v1;
        __syncthreads();
        for (int o = 128; o > 0; o >>= 1) {
            if (tid < o) red[tid] += red[tid + o];
            __syncthreads();
        }
        float inv = 1.0f / fmaxf(sqrtf(red[0]), 1e-8f);
        if (cnt > 0) {
            g_p[side][k * CDIM + tid]       = v0 * inv;
            g_p[side][k * CDIM + tid + 256] = v1 * inv;
        }
    }
}

// ---------------- losses ----------------
__global__ void loss_kernel() {
    int s = blockIdx.x;
    int tid = threadIdx.x;  // 256
    __shared__ float posf[CDIM], negf[CDIM], dsm[192];
    posf[tid]       = g_feats[0][s * CDIM + tid];
    posf[tid + 256] = g_feats[0][s * CDIM + tid + 256];
    negf[tid]       = g_feats[1][s * CDIM + tid];
    negf[tid + 256] = g_feats[1][s * CDIM + tid + 256];
    __syncthreads();
    if (tid < 192) {
        int kind = tid / 64, j = tid % 64;
        const float* f = (kind == 2) ? negf : posf;
        const float* p = ((kind == 1) ? g_p[1] : g_p[0]) + j * CDIM;
        float d = 0.f;
        for (int c = 0; c < CDIM; c += 4) {
            float4 pv = *(const float4*)(p + c);
            d = fmaf(f[c], pv.x, fmaf(f[c+1], pv.y, fmaf(f[c+2], pv.z, fmaf(f[c+3], pv.w, d))));
        }
        dsm[tid] = d;
    }
    __syncthreads();
    if (tid == 0) {
        float mp = dsm[0];
        for (int j = 1; j < 64; j++) mp = fmaxf(mp, dsm[j]);
        float mb = dsm[64];
        for (int j = 65; j < 128; j++) mb = fmaxf(mb, dsm[j]);
        float mn = dsm[128];
        for (int j = 129; j < 192; j++) mn = fmaxf(mn, dsm[j]);
        g_simpos[s] = mp;
        g_simneg[s] = mn;
        float a1 = mp / TAU;
        float sum1 = 0.f;
        for (int j = 0; j < 64; j++) sum1 += expf(dsm[j] / TAU - a1);
        float aall = fmaxf(mp, mb) / TAU;
        float sum2 = 0.f;
        for (int j = 0; j < 128; j++) sum2 += expf(dsm[j] / TAU - aall);
        g_info[s] = (aall + logf(sum2)) - (a1 + logf(sum1));
    }
}

__global__ void finalize_kernel(float* __restrict__ out) {
    int tid = threadIdx.x;  // 256
    __shared__ float r1[256], r2[256], r3[256];
    r1[tid] = g_simpos[tid];
    r2[tid] = g_simneg[tid];
    r3[tid] = g_info[tid];
    __syncthreads();
    for (int o = 128; o > 0; o >>= 1) {
        if (tid < o) { r1[tid] += r1[tid+o]; r2[tid] += r2[tid+o]; r3[tid] += r3[tid+o]; }
        __syncthreads();
    }
    if (tid == 0) {
        float mp = r1[0] / (float)NSEL;
        float mn = r2[0] / (float)NSEL;
        float mi = r3[0] / (float)NSEL;
        out[0] = fmaxf(0.f, MARGIN + mn - mp) + 0.25f * mi;
    }
}

__global__ void refined_kernel(const float* __restrict__ fg, const float* __restrict__ bg,
                               float* __restrict__ out) {
    int k = blockIdx.x, side = blockIdx.y, c = threadIdx.x;  // 512 threads
    const float* src = side ? bg : fg;
    float v = (1.0f - MBLEND) * src[k * CDIM + c] + MBLEND * g_p[side][k * CDIM + c];
    __shared__ float red[CDIM];
    red[c] = v * v;
    __syncthreads();
    for (int o = 256; o > 0; o >>= 1) {
        if (c < o) red[c] += red[c + o];
        __syncthreads();
    }
    float inv = 1.0f / fmaxf(sqrtf(red[0]), 1e-8f);
    out[1 + side * (KP * CDIM) + k * CDIM + c] = v * inv;
}

// ---------------- launch ----------------
extern "C" void kernel_launch(void* const* d_in, const int* in_sizes, int n_in,
                              void* d_out, int out_size) {
    const float* fg = (const float*)d_in[0];
    const float* bg = (const float*)d_in[1];
    const float* F  = (const float*)d_in[2];
    const float* M  = (const float*)d_in[3];
    float* out = (float*)d_out;

    cudaFuncSetAttribute(score_tc, cudaFuncAttributeMaxDynamicSharedMemorySize, SCORE_SMEM);

    prep_wt<<<128, 512>>>(fg, bg);
    prep_wb16<<<128, 128>>>(fg, bg);
    zero_aux<<<128, 256>>>();
    score_tc<<<NP / 128, 256, SCORE_SMEM>>>(F, M);
    hist16_kernel<<<dim3(NP / 256, 2), 256>>>();
    pick16_kernel<<<2, 256>>>();
    hist8_kernel<<<dim3(NP / 256, 2), 256>>>();
    pick8_kernel<<<2, 32>>>();
    collect_kernel<<<dim3(NP / 256, 2), 256>>>();
    rescore_kernel<<<dim3(CAP / 16, 2), 256>>>(F, M);
    select256_kernel<<<2, 256>>>();
    gather_kernel<<<dim3(NSEL, 2), 128>>>(F);
    init_p<<<dim3(KP, 2), 512>>>(fg, bg);
    for (int it = 0; it < NREF; it++) {
        float step = 0.1f / (1.0f + 0.5f * (float)it);
        refine_iter<<<RFB, 256>>>(step);
    }
    loss_kernel<<<NSEL, 256>>>();
    finalize_kernel<<<1, 256>>>(out);
    refined_kernel<<<dim3(KP, 2), 512>>>(fg, bg, out);
}

// round 14
// speedup vs baseline: 1.1521x; 1.0104x over previous
#include <cuda_runtime.h>
#include <cuda_bf16.h>
#include <math.h>

#define NP      147456      // 16*96*96
#define HW      9216        // 96*96
#define CDIM    512
#define KP      64          // protos per side
#define NSEL    256
#define NREF    10
#define TAU     0.07f
#define MARGIN  0.2f
#define MBLEND  0.3f

#define NCAND   2048        // approx-candidate target per side
#define CAP     2560        // candidate buffer cap (headroom for boundary ties)

// ---------------- scratch ----------------
__device__ float    g_Wt[CDIM * 128];         // [c][j] fp32 transposed protos (rescore)
__device__ unsigned g_Wb16u[128 * 256];       // [proto][ch-pair] bf16x2 protos
__device__ float    g_score[2][NP];           // approx scores (bf16 MMA)
__device__ unsigned g_hist16[2][65536];
__device__ unsigned g_hist8[2][256];
__device__ int      g_thr16[2];
__device__ int      g_rem[2];
__device__ unsigned g_thr24[2];
__device__ int      g_ccnt[2];
__device__ int      g_cand[2][CAP];
__device__ float    g_cscore[2][CAP];
__device__ int      g_idx[2][NSEL];
__device__ float    g_feats[2][NSEL * CDIM];
__device__ float    g_p[2][KP * CDIM];
__device__ int      g_assign[2][NSEL];
__device__ float    g_simpos[NSEL], g_simneg[NSEL], g_info[NSEL];

// ---------------- helpers ----------------
__device__ __forceinline__ unsigned mapf(float x) {
    unsigned u = __float_as_uint(x);
    return (u & 0x80000000u) ? ~u : (u | 0x80000000u);
}
__device__ __forceinline__ unsigned pack_bf2(float lo, float hi) {
    unsigned r;
    asm("cvt.rn.bf16x2.f32 %0, %1, %2;" : "=r"(r) : "f"(hi), "f"(lo));
    return r;
}
__device__ __forceinline__ void mma16816(float* c, const unsigned* a, unsigned b0, unsigned b1) {
    asm volatile("mma.sync.aligned.m16n8k16.row.col.f32.bf16.bf16.f32 "
                 "{%0,%1,%2,%3}, {%4,%5,%6,%7}, {%8,%9}, {%0,%1,%2,%3};"
                 : "+f"(c[0]), "+f"(c[1]), "+f"(c[2]), "+f"(c[3])
                 : "r"(a[0]), "r"(a[1]), "r"(a[2]), "r"(a[3]), "r"(b0), "r"(b1));
}
__device__ __forceinline__ unsigned sptr(const void* p) {
    return (unsigned)__cvta_generic_to_shared(p);
}
__device__ __forceinline__ void cp16_cg(unsigned s, const void* g) {
    asm volatile("cp.async.cg.shared.global [%0], [%1], 16;" :: "r"(s), "l"(g));
}
__device__ __forceinline__ void cp16_ca(unsigned s, const void* g) {
    asm volatile("cp.async.ca.shared.global [%0], [%1], 16;" :: "r"(s), "l"(g));
}

// ---------------- kernel: fused prep (Wt transpose + bf16 pack + zero hists) ----------------
__global__ void prep_all(const float* __restrict__ fg, const float* __restrict__ bg) {
    int gid = blockIdx.x * 256 + threadIdx.x;   // 65536 threads
    ((unsigned*)&g_hist16[0][0])[gid] = 0u;
    ((unsigned*)&g_hist16[0][0])[gid + 65536] = 0u;
    if (gid < 512) (&g_hist8[0][0])[gid] = 0u;
    if (gid < 2) g_ccnt[gid] = 0;
    {
        int c = gid >> 7, j = gid & 127;
        float v = (j < KP) ? fg[j * CDIM + c] : bg[(j - KP) * CDIM + c];
        g_Wt[gid] = v;
    }
    if (gid < 32768) {
        int j = gid >> 8, cp = gid & 255;
        const float* src = (j < KP) ? (fg + j * CDIM) : (bg + (j - KP) * CDIM);
        g_Wb16u[gid] = pack_bf2(src[cp * 2], src[cp * 2 + 1]);
    }
}

// ---------------- approx score: bf16 TC GEMM, cp.async 3-stage pipeline ----------------
// block = 128 px x 128 protos, 256 threads (8 warps: 4M x 2N), K chunk 32, 16 chunks
// dyn smem: Af32[3][32*128] f32 | Wst[3][128*20] u32 | As32[128*20] u32 | normsh[128] f32
#define SCORE_SMEM (49152 + 30720 + 10240 + 512)
__global__ __launch_bounds__(256, 2) void score_tc(
    const float* __restrict__ F, const float* __restrict__ M) {
    extern __shared__ char smem_raw[];
    float*    Af32   = (float*)smem_raw;                          // 3 x 16 KB
    unsigned* Wst    = (unsigned*)(smem_raw + 49152);             // 3 x 10 KB
    unsigned* As32   = (unsigned*)(smem_raw + 49152 + 30720);     // 10 KB
    float*    normsh = (float*)(smem_raw + 49152 + 30720 + 10240);

    int tid = threadIdx.x, lane = tid & 31, w = tid >> 5;
    int wm = w >> 1, wn = w & 1;
    int gpix0 = blockIdx.x * 128;
    int n = gpix0 / HW, hw0 = gpix0 - n * HW;
    const float* Fb = F + (size_t)n * CDIM * HW + hw0;

    if (tid < 128) normsh[tid] = 0.f;

    float acc[2][8][4];
#pragma unroll
    for (int a = 0; a < 2; a++)
#pragma unroll
        for (int b = 0; b < 8; b++)
#pragma unroll
            for (int d = 0; d < 4; d++) acc[a][b][d] = 0.f;

    int px = tid & 127, half = tid >> 7;
    float mynrm = 0.f;

    auto issue_chunk = [&](int ic) {
        int buf = ic % 3;
        int c0 = ic * 32;
        float* Ad = Af32 + buf * (32 * 128);
#pragma unroll
        for (int j = 0; j < 4; j++) {
            int idx = tid + 256 * j;
            int r = idx >> 5, sg = idx & 31;
            cp16_cg(sptr(Ad + r * 128 + sg * 4),
                    Fb + (size_t)(c0 + r) * HW + sg * 4);
        }
        unsigned* Wd = Wst + buf * (128 * 20);
#pragma unroll
        for (int j = 0; j < 2; j++) {
            int idx = tid + 256 * j;
            int p = idx >> 2, sg = idx & 3;
            cp16_ca(sptr(Wd + p * 20 + sg * 4),
                    g_Wb16u + p * 256 + (c0 >> 1) + sg * 4);
        }
        asm volatile("cp.async.commit_group;");
    };

    issue_chunk(0);
    issue_chunk(1);
    issue_chunk(2);

    int g = lane >> 2, t4 = lane & 3;
    for (int ic = 0; ic < 16; ic++) {
        int buf = ic % 3;
        int rem = 15 - ic;            // chunks still outstanding beyond ic
        if (rem >= 2)      asm volatile("cp.async.wait_group 2;");
        else if (rem == 1) asm volatile("cp.async.wait_group 1;");
        else               asm volatile("cp.async.wait_group 0;");
        __syncthreads();

        {
            const float* Asrc = Af32 + buf * (32 * 128);
#pragma unroll
            for (int kp = 0; kp < 8; kp++) {
                int k = (half * 8 + kp) * 2;
                float v0 = Asrc[k * 128 + px];
                float v1 = Asrc[(k + 1) * 128 + px];
                mynrm += v0 * v0 + v1 * v1;
                As32[px * 20 + half * 8 + kp] = pack_bf2(v0, v1);
            }
        }
        __syncthreads();

        {
            const unsigned* Ws = Wst + buf * (128 * 20);
#pragma unroll
            for (int k16 = 0; k16 < 2; k16++) {
                unsigned a[2][4];
#pragma unroll
                for (int mt = 0; mt < 2; mt++) {
                    int row = wm * 32 + mt * 16 + g;
                    int base = row * 20 + k16 * 8 + t4;
                    a[mt][0] = As32[base];
                    a[mt][1] = As32[base + 8 * 20];
                    a[mt][2] = As32[base + 4];
                    a[mt][3] = As32[base + 8 * 20 + 4];
                }
#pragma unroll
                for (int nt = 0; nt < 8; nt++) {
                    int pr = wn * 64 + nt * 8 + g;
                    int bb = pr * 20 + k16 * 8 + t4;
                    unsigned b0 = Ws[bb], b1 = Ws[bb + 4];
#pragma unroll
                    for (int mt = 0; mt < 2; mt++) mma16816(acc[mt][nt], a[mt], b0, b1);
                }
            }
        }
        __syncthreads();
        if (ic + 3 < 16) issue_chunk(ic + 3);
    }

    atomicAdd(&normsh[px], mynrm);
    __syncthreads();

#pragma unroll
    for (int mt = 0; mt < 2; mt++) {
#pragma unroll
        for (int h = 0; h < 2; h++) {
            float m = -1e30f;
#pragma unroll
            for (int nt = 0; nt < 8; nt++)
                m = fmaxf(m, fmaxf(acc[mt][nt][h * 2], acc[mt][nt][h * 2 + 1]));
            m = fmaxf(m, __shfl_xor_sync(0xFFFFFFFFu, m, 1));
            m = fmaxf(m, __shfl_xor_sync(0xFFFFFFFFu, m, 2));
            if ((lane & 3) == 0) {
                int p = wm * 32 + mt * 16 + h * 8 + g;
                float inv = 1.0f / fmaxf(sqrtf(normsh[p]), 1e-8f);
                float sim = m * inv;
                float mv = fminf(fmaxf(M[gpix0 + p], 0.f), 1.f);
                float d = 1.0f - sim;
                g_score[wn][gpix0 + p] = (wn == 0) ? d * mv : d * (1.0f - mv);
            }
        }
    }
}

// ---------------- candidate selection (grid-parallel) ----------------
__global__ void hist16_kernel() {
    int side = blockIdx.y;
    int i = blockIdx.x * 256 + threadIdx.x;
    unsigned key = mapf(g_score[side][i]);
    atomicAdd(&g_hist16[side][key >> 16], 1u);
}

__global__ void pick16_kernel() {
    int side = blockIdx.x, tid = threadIdx.x;
    __shared__ unsigned ps[256];
    unsigned s = 0;
    for (int b = tid * 256; b < tid * 256 + 256; b++) s += g_hist16[side][b];
    ps[tid] = s;
    __syncthreads();
    if (tid == 0) {
        unsigned cum = 0;
        int seg = 255;
        for (; seg >= 0; seg--) {
            if (cum + ps[seg] >= (unsigned)NCAND) break;
            cum += ps[seg];
        }
        int b;
        for (b = seg * 256 + 255; b > seg * 256; b--) {
            unsigned h = g_hist16[side][b];
            if (cum + h >= (unsigned)NCAND) break;
            cum += h;
        }
        g_thr16[side] = b;
        g_rem[side] = NCAND - (int)cum;
    }
}

__global__ void hist8_kernel() {
    int side = blockIdx.y;
    int i = blockIdx.x * 256 + threadIdx.x;
    unsigned key = mapf(g_score[side][i]);
    if ((int)(key >> 16) == g_thr16[side])
        atomicAdd(&g_hist8[side][(key >> 8) & 255], 1u);
}

__global__ void pick8_kernel() {
    int side = blockIdx.x;
    if (threadIdx.x == 0) {
        int rem = g_rem[side];
        unsigned cum = 0;
        int b;
        for (b = 255; b > 0; b--) {
            unsigned h = g_hist8[side][b];
            if (cum + h >= (unsigned)rem) break;
            cum += h;
        }
        g_thr24[side] = (((unsigned)g_thr16[side]) << 8) | (unsigned)b;
    }
}

__global__ void collect_kernel() {
    int side = blockIdx.y;
    int i = blockIdx.x * 256 + threadIdx.x;
    unsigned key24 = mapf(g_score[side][i]) >> 8;
    if (key24 >= g_thr24[side]) {
        int pos = atomicAdd(&g_ccnt[side], 1);
        if (pos < CAP) g_cand[side][pos] = i;
    }
}

// ---------------- exact FP32 rescore: 16 candidates per block ----------------
__global__ __launch_bounds__(256) void rescore_kernel(
    const float* __restrict__ F, const float* __restrict__ M) {
    int side = blockIdx.y;
    int s0 = blockIdx.x * 16;
    int tid = threadIdx.x, lane = tid & 31, w = tid >> 5;
    int cnt = min(g_ccnt[side], CAP);

    if (s0 >= cnt) {
        if (tid < 16) g_cscore[side][s0 + tid] = -3.0e38f;
        return;
    }

    __shared__ float fsh[16][CDIM];
    __shared__ float nrm[16];

#pragma unroll
    for (int h = 0; h < 2; h++) {
        int cslot = 2 * w + h;
        int s = s0 + cslot;
        bool valid = (s < cnt);
        int idx = g_cand[side][valid ? s : 0];
        int n = idx / HW, hw = idx - n * HW;
        const float* base = F + (size_t)n * CDIM * HW + hw;
        float partial = 0.f;
#pragma unroll
        for (int i = 0; i < 16; i++) {
            int c = lane + 32 * i;
            float v = base[(size_t)c * HW];
            fsh[cslot][c] = v;
            partial += v * v;
        }
#pragma unroll
        for (int o = 16; o > 0; o >>= 1)
            partial += __shfl_xor_sync(0xFFFFFFFFu, partial, o);
        if (lane == 0) nrm[cslot] = partial;
    }
    __syncthreads();

    int half = lane >> 4, l16 = lane & 15;
    int cslot = 2 * w + half;
    const float* Wb = g_Wt + side * 64 + l16 * 4;
    float d0 = 0.f, d1 = 0.f, d2 = 0.f, d3 = 0.f;
#pragma unroll 4
    for (int c = 0; c < CDIM; c++) {
        float f = fsh[cslot][c];
        float4 wv = *(const float4*)(Wb + (size_t)c * 128);
        d0 = fmaf(f, wv.x, d0);
        d1 = fmaf(f, wv.y, d1);
        d2 = fmaf(f, wv.z, d2);
        d3 = fmaf(f, wv.w, d3);
    }
    float m = fmaxf(fmaxf(d0, d1), fmaxf(d2, d3));
#pragma unroll
    for (int o = 8; o > 0; o >>= 1)
        m = fmaxf(m, __shfl_xor_sync(0xFFFFFFFFu, m, o));
    if (l16 == 0) {
        int s = s0 + cslot;
        bool valid = (s < cnt);
        float val = -3.0e38f;
        if (valid) {
            int idx = g_cand[side][s];
            float inv = 1.0f / fmaxf(sqrtf(nrm[cslot]), 1e-8f);
            float sim = m * inv;
            float mv = fminf(fmaxf(M[idx], 0.f), 1.f);
            val = (side == 0) ? (1.0f - sim) * mv : (1.0f - sim) * (1.0f - mv);
        }
        g_cscore[side][s] = val;
    }
}

// ---------------- exact top-256 among candidates ----------------
__global__ void select256_kernel() {
    int side = blockIdx.x, tid = threadIdx.x;
    const float* sc = g_cscore[side];
    const int* cd = g_cand[side];
    __shared__ unsigned hist[256];
    __shared__ unsigned sh_pfx, sh_dmask;
    __shared__ int sh_krem, gcnt, tcnt;
    __shared__ int glist[NSEL];
    __shared__ int ties[CAP];

    if (tid == 0) { sh_pfx = 0; sh_dmask = 0; sh_krem = NSEL; }
    __syncthreads();
    for (int shift = 24; shift >= 0; shift -= 8) {
        if (tid < 256) hist[tid] = 0;
        __syncthreads();
        unsigned dm = sh_dmask, pf = sh_pfx;
        for (int i = tid; i < CAP; i += blockDim.x) {
            unsigned key = mapf(sc[i]);
            if ((key & dm) == pf) atomicAdd(&hist[(key >> shift) & 255], 1u);
        }
        __syncthreads();
        if (tid == 0) {
            int kr = sh_krem;
            unsigned cum = 0;
            int d = 255;
            for (; d > 0; d--) {
                if (cum + hist[d] >= (unsigned)kr) break;
                cum += hist[d];
            }
            sh_krem  = kr - (int)cum;
            sh_pfx   = sh_pfx | ((unsigned)d << shift);
            sh_dmask = sh_dmask | (0xFFu << shift);
        }
        __syncthreads();
    }
    if (tid == 0) { gcnt = 0; tcnt = 0; }
    __syncthreads();
    unsigned thr = sh_pfx;
    for (int i = tid; i < CAP; i += blockDim.x) {
        unsigned key = mapf(sc[i]);
        if (key > thr) {
            int p = atomicAdd(&gcnt, 1);
            if (p < NSEL) glist[p] = cd[i];
        } else if (key == thr) {
            int p = atomicAdd(&tcnt, 1);
            if (p < CAP) ties[p] = cd[i];
        }
    }
    __syncthreads();
    int G = min(gcnt, NSEL);
    for (int e = tid; e < G; e += blockDim.x) {
        int pe = glist[e], r = 0;
        for (int j = 0; j < G; j++) r += (glist[j] < pe);
        g_idx[side][r] = pe;
    }
    int need = NSEL - G;
    int T = min(tcnt, CAP);
    for (int e = tid; e < T; e += blockDim.x) {
        int pe = ties[e], r = 0;
        for (int j = 0; j < T; j++) r += (ties[j] < pe);
        if (r < need) g_idx[side][G + r] = pe;
    }
}

// ---------------- gather + normalize selected features ----------------
__global__ void gather_kernel(const float* __restrict__ F) {
    int s = blockIdx.x, side = blockIdx.y;
    int idx = g_idx[side][s];
    int n = idx / HW, hw = idx - n * HW;
    const float* base = F + (size_t)n * CDIM * HW + hw;
    int tid = threadIdx.x;  // 128
    float v[4], ss = 0.f;
#pragma unroll
    for (int i = 0; i < 4; i++) {
        int c = tid + i * 128;
        v[i] = base[(size_t)c * HW];
        ss += v[i] * v[i];
    }
#pragma unroll
    for (int o = 16; o > 0; o >>= 1) ss += __shfl_xor_sync(0xFFFFFFFFu, ss, o);
    __shared__ float wsum[4];
    if ((tid & 31) == 0) wsum[tid >> 5] = ss;
    __syncthreads();
    float inv = 1.0f / fmaxf(sqrtf(wsum[0] + wsum[1] + wsum[2] + wsum[3]), 1e-8f);
#pragma unroll
    for (int i = 0; i < 4; i++)
        g_feats[side][s * CDIM + tid + i * 128] = v[i] * inv;
}

__global__ void init_p(const float* __restrict__ fg, const float* __restrict__ bg) {
    int k = blockIdx.x, side = blockIdx.y, c = threadIdx.x;
    const float* src = side ? bg : fg;
    g_p[side][k * CDIM + c] = src[k * CDIM + c];
}

// ---------------- refinement (R11 structure) ----------------
__global__ void assign_kernel() {
    int side = blockIdx.y;
    int s0 = blockIdx.x * 8;
    __shared__ float fsm[8 * CDIM];
    __shared__ float dsm[8][KP];
    int tid = threadIdx.x;  // 256
    const float4* src = (const float4*)(g_feats[side] + s0 * CDIM);
#pragma unroll
    for (int i = 0; i < 4; i++)
        ((float4*)fsm)[tid + 256 * i] = src[tid + 256 * i];
    __syncthreads();
    int j = tid & 63, sg = tid >> 6;
    const float* pj = g_p[side] + j * CDIM;
    const float* fa = fsm + (sg * 2) * CDIM;
    const float* fb = fa + CDIM;
    float d0 = 0.f, d1 = 0.f;
    for (int c = 0; c < CDIM; c += 4) {
        float4 pv = *(const float4*)(pj + c);
        float4 av = *(const float4*)(fa + c);
        float4 bv = *(const float4*)(fb + c);
        d0 = fmaf(av.x, pv.x, fmaf(av.y, pv.y, fmaf(av.z, pv.z, fmaf(av.w, pv.w, d0))));
        d1 = fmaf(bv.x, pv.x, fmaf(bv.y, pv.y, fmaf(bv.z, pv.z, fmaf(bv.w, pv.w, d1))));
    }
    dsm[sg * 2][j] = d0;
    dsm[sg * 2 + 1][j] = d1;
    __syncthreads();
    if (tid < 8) {
        float best = dsm[tid][0];
        int bj = 0;
        for (int jj = 1; jj < KP; jj++) {
            float v = dsm[tid][jj];
            if (v > best) { best = v; bj = jj; }
        }
        g_assign[side][s0 + tid] = bj;
    }
}

__global__ void update_kernel(float step) {
    int k = blockIdx.x, side = blockIdx.y;
    int tid = threadIdx.x;  // 256
    __shared__ int asg[NSEL];
    __shared__ float red[256];
    asg[tid] = g_assign[side][tid];
    __syncthreads();
    int c = tid;
    float s0 = 0.f, s1 = 0.f;
    int cnt = 0;
    for (int s = 0; s < NSEL; s++) {
        if (asg[s] == k) {
            cnt++;
            const float* f = g_feats[side] + s * CDIM;
            s0 += f[c];
            s1 += f[c + 256];
        }
    }
    float denom = fmaxf((float)cnt, 1.0f);
    float p0 = g_p[side][k * CDIM + c];
    float p1 = g_p[side][k * CDIM + c + 256];
    float v0 = (1.0f - step) * p0 + step * (s0 / denom);
    float v1 = (1.0f - step) * p1 + step * (s1 / denom);
    red[tid] = v0 * v0 + v1 * v1;
    __syncthreads();
    for (int o = 128; o > 0; o >>= 1) {
        if (tid < o) red[tid] += red[tid + o];
        __syncthreads();
    }
    float inv = 1.0f / fmaxf(sqrtf(red[0]), 1e-8f);
    if (cnt > 0) {
        g_p[side][k * CDIM + c]       = v0 * inv;
        g_p[side][k * CDIM + c + 256] = v1 * inv;
    }
}

// ---------------- losses ----------------
__global__ void loss_kernel() {
    int s = blockIdx.x;
    int tid = threadIdx.x;  // 256
    __shared__ float posf[CDIM], negf[CDIM], dsm[192];
    posf[tid]       = g_feats[0][s * CDIM + tid];
    posf[tid + 256] = g_feats[0][s * CDIM + tid + 256];
    negf[tid]       = g_feats[1][s * CDIM + tid];
    negf[tid + 256] = g_feats[1][s * CDIM + tid + 256];
    __syncthreads();
    if (tid < 192) {
        int kind = tid / 64, j = tid % 64;
        const float* f = (kind == 2) ? negf : posf;
        const float* p = ((kind == 1) ? g_p[1] : g_p[0]) + j * CDIM;
        float d = 0.f;
        for (int c = 0; c < CDIM; c += 4) {
            float4 pv = *(const float4*)(p + c);
            d = fmaf(f[c], pv.x, fmaf(f[c+1], pv.y, fmaf(f[c+2], pv.z, fmaf(f[c+3], pv.w, d))));
        }
        dsm[tid] = d;
    }
    __syncthreads();
    if (tid == 0) {
        float mp = dsm[0];
        for (int j = 1; j < 64; j++) mp = fmaxf(mp, dsm[j]);
        float mb = dsm[64];
        for (int j = 65; j < 128; j++) mb = fmaxf(mb, dsm[j]);
        float mn = dsm[128];
        for (int j = 129; j < 192; j++) mn = fmaxf(mn, dsm[j]);
        g_simpos[s] = mp;
        g_simneg[s] = mn;
        float a1 = mp / TAU;
        float sum1 = 0.f;
        for (int j = 0; j < 64; j++) sum1 += expf(dsm[j] / TAU - a1);
        float aall = fmaxf(mp, mb) / TAU;
        float sum2 = 0.f;
        for (int j = 0; j < 128; j++) sum2 += expf(dsm[j] / TAU - aall);
        g_info[s] = (aall + logf(sum2)) - (a1 + logf(sum1));
    }
}

__global__ void finalize_kernel(float* __restrict__ out) {
    int tid = threadIdx.x;  // 256
    __shared__ float r1[256], r2[256], r3[256];
    r1[tid] = g_simpos[tid];
    r2[tid] = g_simneg[tid];
    r3[tid] = g_info[tid];
    __syncthreads();
    for (int o = 128; o > 0; o >>= 1) {
        if (tid < o) { r1[tid] += r1[tid+o]; r2[tid] += r2[tid+o]; r3[tid] += r3[tid+o]; }
        __syncthreads();
    }
    if (tid == 0) {
        float mp = r1[0] / (float)NSEL;
        float mn = r2[0] / (float)NSEL;
        float mi = r3[0] / (float)NSEL;
        out[0] = fmaxf(0.f, MARGIN + mn - mp) + 0.25f * mi;
    }
}

__global__ void refined_kernel(const float* __restrict__ fg, const float* __restrict__ bg,
                               float* __restrict__ out) {
    int k = blockIdx.x, side = blockIdx.y, c = threadIdx.x;  // 512 threads
    const float* src = side ? bg : fg;
    float v = (1.0f - MBLEND) * src[k * CDIM + c] + MBLEND * g_p[side][k * CDIM + c];
    __shared__ float red[CDIM];
    red[c] = v * v;
    __syncthreads();
    for (int o = 256; o > 0; o >>= 1) {
        if (c < o) red[c] += red[c + o];
        __syncthreads();
    }
    float inv = 1.0f / fmaxf(sqrtf(red[0]), 1e-8f);
    out[1 + side * (KP * CDIM) + k * CDIM + c] = v * inv;
}

// ---------------- launch ----------------
extern "C" void kernel_launch(void* const* d_in, const int* in_sizes, int n_in,
                              void* d_out, int out_size) {
    const float* fg = (const float*)d_in[0];
    const float* bg = (const float*)d_in[1];
    const float* F  = (const float*)d_in[2];
    const float* M  = (const float*)d_in[3];
    float* out = (float*)d_out;

    cudaFuncSetAttribute(score_tc, cudaFuncAttributeMaxDynamicSharedMemorySize, SCORE_SMEM);

    prep_all<<<256, 256>>>(fg, bg);
    score_tc<<<NP / 128, 256, SCORE_SMEM>>>(F, M);
    hist16_kernel<<<dim3(NP / 256, 2), 256>>>();
    pick16_kernel<<<2, 256>>>();
    hist8_kernel<<<dim3(NP / 256, 2), 256>>>();
    pick8_kernel<<<2, 32>>>();
    collect_kernel<<<dim3(NP / 256, 2), 256>>>();
    rescore_kernel<<<dim3(CAP / 16, 2), 256>>>(F, M);
    select256_kernel<<<2, 256>>>();
    gather_kernel<<<dim3(NSEL, 2), 128>>>(F);
    init_p<<<dim3(KP, 2), 512>>>(fg, bg);
    for (int it = 0; it < NREF; it++) {
        float step = 0.1f / (1.0f + 0.5f * (float)it);
        assign_kernel<<<dim3(NSEL / 8, 2), 256>>>();
        update_kernel<<<dim3(KP, 2), 256>>>(step);
    }
    loss_kernel<<<NSEL, 256>>>();
    finalize_kernel<<<1, 256>>>(out);
    refined_kernel<<<dim3(KP, 2), 512>>>(fg, bg, out);
}

// round 15
// speedup vs baseline: 1.2390x; 1.0754x over previous
#include <cuda_runtime.h>
#include <cuda_bf16.h>
#include <math.h>

#define NP      147456      // 16*96*96
#define HW      9216        // 96*96
#define CDIM    512
#define KP      64          // protos per side
#define NSEL    256
#define NREF    10
#define TAU     0.07f
#define MARGIN  0.2f
#define MBLEND  0.3f

#define NCAND   2048        // approx-candidate target per side
#define CAP     2560        // candidate buffer cap

// ---------------- scratch ----------------
__device__ float    g_Wt[CDIM * 128];
__device__ unsigned g_Wb16u[128 * 256];
__device__ float    g_score[2][NP];
__device__ unsigned g_hist16[2][65536];
__device__ unsigned g_hist8[2][256];
__device__ int      g_thr16[2];
__device__ int      g_rem[2];
__device__ unsigned g_thr24[2];
__device__ int      g_ccnt[2];
__device__ int      g_cand[2][CAP];
__device__ float    g_cscore[2][CAP];
__device__ int      g_idx[2][NSEL];
__device__ float    g_feats[2][NSEL * CDIM];
__device__ float    g_p[2][KP * CDIM];
__device__ int      g_assign[2][NSEL];
__device__ float    g_simpos[NSEL], g_simneg[NSEL], g_info[NSEL];

// ---------------- helpers ----------------
__device__ __forceinline__ unsigned mapf(float x) {
    unsigned u = __float_as_uint(x);
    return (u & 0x80000000u) ? ~u : (u | 0x80000000u);
}
__device__ __forceinline__ unsigned pack_bf2(float lo, float hi) {
    unsigned r;
    asm("cvt.rn.bf16x2.f32 %0, %1, %2;" : "=r"(r) : "f"(hi), "f"(lo));
    return r;
}
__device__ __forceinline__ void mma16816(float* c, const unsigned* a, unsigned b0, unsigned b1) {
    asm volatile("mma.sync.aligned.m16n8k16.row.col.f32.bf16.bf16.f32 "
                 "{%0,%1,%2,%3}, {%4,%5,%6,%7}, {%8,%9}, {%0,%1,%2,%3};"
                 : "+f"(c[0]), "+f"(c[1]), "+f"(c[2]), "+f"(c[3])
                 : "r"(a[0]), "r"(a[1]), "r"(a[2]), "r"(a[3]), "r"(b0), "r"(b1));
}
__device__ __forceinline__ unsigned sptr(const void* p) {
    return (unsigned)__cvta_generic_to_shared(p);
}
__device__ __forceinline__ void cp16_cg(unsigned s, const void* g) {
    asm volatile("cp.async.cg.shared.global [%0], [%1], 16;" :: "r"(s), "l"(g));
}
__device__ __forceinline__ void cp16_ca(unsigned s, const void* g) {
    asm volatile("cp.async.ca.shared.global [%0], [%1], 16;" :: "r"(s), "l"(g));
}

// ---------------- prep (R11-verified) ----------------
__global__ void prep_wt(const float* __restrict__ fg, const float* __restrict__ bg) {
    int j = blockIdx.x, c = threadIdx.x;
    float v = (j < KP) ? fg[j * CDIM + c] : bg[(j - KP) * CDIM + c];
    g_Wt[c * 128 + j] = v;
}
__global__ void prep_wb16(const float* __restrict__ fg, const float* __restrict__ bg) {
    int j = blockIdx.x, t = threadIdx.x;  // 128 threads
    const float* src = (j < KP) ? (fg + j * CDIM) : (bg + (j - KP) * CDIM);
    int c = t * 4;
    g_Wb16u[j * 256 + t * 2]     = pack_bf2(src[c],     src[c + 1]);
    g_Wb16u[j * 256 + t * 2 + 1] = pack_bf2(src[c + 2], src[c + 3]);
}
__global__ void zero_aux() {
    int t = blockIdx.x * blockDim.x + threadIdx.x;
    unsigned* h16 = &g_hist16[0][0];
    for (int i = t; i < 2 * 65536; i += gridDim.x * blockDim.x) h16[i] = 0;
    if (t < 512) (&g_hist8[0][0])[t] = 0;
    if (t < 2) g_ccnt[t] = 0;
}

// ---------------- approx score: bf16 TC GEMM, cp.async 2-stage (R11-verified) ----------------
#define SCORE_SMEM (32768 + 20480 + 10240 + 512)
__global__ __launch_bounds__(256, 2) void score_tc(
    const float* __restrict__ F, const float* __restrict__ M) {
    extern __shared__ char smem_raw[];
    float*    Af32   = (float*)smem_raw;
    unsigned* Wst    = (unsigned*)(smem_raw + 32768);
    unsigned* As32   = (unsigned*)(smem_raw + 32768 + 20480);
    float*    normsh = (float*)(smem_raw + 63488);

    int tid = threadIdx.x, lane = tid & 31, w = tid >> 5;
    int wm = w >> 1, wn = w & 1;
    int gpix0 = blockIdx.x * 128;
    int n = gpix0 / HW, hw0 = gpix0 - n * HW;
    const float* Fb = F + (size_t)n * CDIM * HW + hw0;

    if (tid < 128) normsh[tid] = 0.f;

    float acc[2][8][4];
#pragma unroll
    for (int a = 0; a < 2; a++)
#pragma unroll
        for (int b = 0; b < 8; b++)
#pragma unroll
            for (int d = 0; d < 4; d++) acc[a][b][d] = 0.f;

    int px = tid & 127, half = tid >> 7;
    float mynrm = 0.f;

    auto issue_chunk = [&](int ic) {
        int buf = ic & 1;
        int c0 = ic * 32;
        float* Ad = Af32 + buf * (32 * 128);
#pragma unroll
        for (int j = 0; j < 4; j++) {
            int idx = tid + 256 * j;
            int r = idx >> 5, sg = idx & 31;
            cp16_cg(sptr(Ad + r * 128 + sg * 4),
                    Fb + (size_t)(c0 + r) * HW + sg * 4);
        }
        unsigned* Wd = Wst + buf * (128 * 20);
#pragma unroll
        for (int j = 0; j < 2; j++) {
            int idx = tid + 256 * j;
            int p = idx >> 2, sg = idx & 3;
            cp16_ca(sptr(Wd + p * 20 + sg * 4),
                    g_Wb16u + p * 256 + (c0 >> 1) + sg * 4);
        }
        asm volatile("cp.async.commit_group;");
    };

    issue_chunk(0);
    issue_chunk(1);

    int g = lane >> 2, t4 = lane & 3;
    for (int ic = 0; ic < 16; ic++) {
        int buf = ic & 1;
        if (ic < 15) asm volatile("cp.async.wait_group 1;");
        else         asm volatile("cp.async.wait_group 0;");
        __syncthreads();

        {
            const float* Asrc = Af32 + buf * (32 * 128);
#pragma unroll
            for (int kp = 0; kp < 8; kp++) {
                int k = (half * 8 + kp) * 2;
                float v0 = Asrc[k * 128 + px];
                float v1 = Asrc[(k + 1) * 128 + px];
                mynrm += v0 * v0 + v1 * v1;
                As32[px * 20 + half * 8 + kp] = pack_bf2(v0, v1);
            }
        }
        __syncthreads();

        {
            const unsigned* Ws = Wst + buf * (128 * 20);
#pragma unroll
            for (int k16 = 0; k16 < 2; k16++) {
                unsigned a[2][4];
#pragma unroll
                for (int mt = 0; mt < 2; mt++) {
                    int row = wm * 32 + mt * 16 + g;
                    int base = row * 20 + k16 * 8 + t4;
                    a[mt][0] = As32[base];
                    a[mt][1] = As32[base + 8 * 20];
                    a[mt][2] = As32[base + 4];
                    a[mt][3] = As32[base + 8 * 20 + 4];
                }
#pragma unroll
                for (int nt = 0; nt < 8; nt++) {
                    int pr = wn * 64 + nt * 8 + g;
                    int bb = pr * 20 + k16 * 8 + t4;
                    unsigned b0 = Ws[bb], b1 = Ws[bb + 4];
#pragma unroll
                    for (int mt = 0; mt < 2; mt++) mma16816(acc[mt][nt], a[mt], b0, b1);
                }
            }
        }
        __syncthreads();
        if (ic + 2 < 16) issue_chunk(ic + 2);
    }

    atomicAdd(&normsh[px], mynrm);
    __syncthreads();

#pragma unroll
    for (int mt = 0; mt < 2; mt++) {
#pragma unroll
        for (int h = 0; h < 2; h++) {
            float m = -1e30f;
#pragma unroll
            for (int nt = 0; nt < 8; nt++)
                m = fmaxf(m, fmaxf(acc[mt][nt][h * 2], acc[mt][nt][h * 2 + 1]));
            m = fmaxf(m, __shfl_xor_sync(0xFFFFFFFFu, m, 1));
            m = fmaxf(m, __shfl_xor_sync(0xFFFFFFFFu, m, 2));
            if ((lane & 3) == 0) {
                int p = wm * 32 + mt * 16 + h * 8 + g;
                float inv = 1.0f / fmaxf(sqrtf(normsh[p]), 1e-8f);
                float sim = m * inv;
                float mv = fminf(fmaxf(M[gpix0 + p], 0.f), 1.f);
                float d = 1.0f - sim;
                g_score[wn][gpix0 + p] = (wn == 0) ? d * mv : d * (1.0f - mv);
            }
        }
    }
}

// ---------------- candidate selection ----------------
__global__ void hist16_kernel() {
    int side = blockIdx.y;
    int i = blockIdx.x * 256 + threadIdx.x;
    unsigned key = mapf(g_score[side][i]);
    atomicAdd(&g_hist16[side][key >> 16], 1u);
}

// pick16 v2: parallel suffix-scan selection (replaces serial global scans)
__global__ void pick16_kernel() {
    int side = blockIdx.x, tid = threadIdx.x;   // 256 threads
    __shared__ unsigned ps[256];
    __shared__ unsigned bins[256];
    __shared__ unsigned suf[256];
    __shared__ int sh_seg;

    // segment sums: thread t sums bins [t*256, t*256+256) with uint4 loads
    {
        const uint4* h4 = (const uint4*)&g_hist16[side][tid * 256];
        unsigned s = 0;
#pragma unroll 16
        for (int i = 0; i < 64; i++) {
            uint4 v = h4[i];
            s += v.x + v.y + v.z + v.w;
        }
        ps[tid] = s;
    }
    __syncthreads();
    // suffix-sum over segments
    for (int o = 1; o < 256; o <<= 1) {
        unsigned add = (tid + o < 256) ? ps[tid + o] : 0u;
        __syncthreads();
        ps[tid] += add;
        __syncthreads();
    }
    // seg = max t with suffix(t) >= NCAND
    if (ps[tid] >= (unsigned)NCAND && (tid == 255 || ps[tid + 1] < (unsigned)NCAND))
        sh_seg = tid;
    __syncthreads();
    int seg = sh_seg;
    unsigned segAbove = (seg == 255) ? 0u : ps[seg + 1];

    // load winning segment's bins, suffix-scan
    bins[tid] = g_hist16[side][seg * 256 + tid];
    __syncthreads();
    suf[tid] = bins[tid];
    __syncthreads();
    for (int o = 1; o < 256; o <<= 1) {
        unsigned add = (tid + o < 256) ? suf[tid + o] : 0u;
        __syncthreads();
        suf[tid] += add;
        __syncthreads();
    }
    // b = max t with segAbove + suffix(t) >= NCAND
    unsigned need = (unsigned)NCAND - segAbove;   // >=1 by construction of seg
    if (suf[tid] >= need && (tid == 255 || suf[tid + 1] < need)) {
        g_thr16[side] = seg * 256 + tid;
        unsigned above = segAbove + ((tid == 255) ? 0u : suf[tid + 1]);
        g_rem[side] = NCAND - (int)above;
    }
}

__global__ void hist8_kernel() {
    int side = blockIdx.y;
    int i = blockIdx.x * 256 + threadIdx.x;
    unsigned key = mapf(g_score[side][i]);
    if ((int)(key >> 16) == g_thr16[side])
        atomicAdd(&g_hist8[side][(key >> 8) & 255], 1u);
}

// pick8 v2: parallel suffix-scan
__global__ void pick8_kernel() {
    int side = blockIdx.x, tid = threadIdx.x;   // 256 threads
    __shared__ unsigned suf[256];
    suf[tid] = g_hist8[side][tid];
    __syncthreads();
    for (int o = 1; o < 256; o <<= 1) {
        unsigned add = (tid + o < 256) ? suf[tid + o] : 0u;
        __syncthreads();
        suf[tid] += add;
        __syncthreads();
    }
    unsigned rem = (unsigned)g_rem[side];
    if (suf[tid] >= rem && (tid == 255 || suf[tid + 1] < rem))
        g_thr24[side] = (((unsigned)g_thr16[side]) << 8) | (unsigned)tid;
}

__global__ void collect_kernel() {
    int side = blockIdx.y;
    int i = blockIdx.x * 256 + threadIdx.x;
    unsigned key24 = mapf(g_score[side][i]) >> 8;
    if (key24 >= g_thr24[side]) {
        int pos = atomicAdd(&g_ccnt[side], 1);
        if (pos < CAP) g_cand[side][pos] = i;
    }
}

// ---------------- exact FP32 rescore: 16 candidates per block (verified) ----------------
__global__ __launch_bounds__(256) void rescore_kernel(
    const float* __restrict__ F, const float* __restrict__ M) {
    int side = blockIdx.y;
    int s0 = blockIdx.x * 16;
    int tid = threadIdx.x, lane = tid & 31, w = tid >> 5;
    int cnt = min(g_ccnt[side], CAP);

    if (s0 >= cnt) {
        if (tid < 16) g_cscore[side][s0 + tid] = -3.0e38f;
        return;
    }

    __shared__ float fsh[16][CDIM];
    __shared__ float nrm[16];

#pragma unroll
    for (int h = 0; h < 2; h++) {
        int cslot = 2 * w + h;
        int s = s0 + cslot;
        bool valid = (s < cnt);
        int idx = g_cand[side][valid ? s : 0];
        int n = idx / HW, hw = idx - n * HW;
        const float* base = F + (size_t)n * CDIM * HW + hw;
        float partial = 0.f;
#pragma unroll
        for (int i = 0; i < 16; i++) {
            int c = lane + 32 * i;
            float v = base[(size_t)c * HW];
            fsh[cslot][c] = v;
            partial += v * v;
        }
#pragma unroll
        for (int o = 16; o > 0; o >>= 1)
            partial += __shfl_xor_sync(0xFFFFFFFFu, partial, o);
        if (lane == 0) nrm[cslot] = partial;
    }
    __syncthreads();

    int half = lane >> 4, l16 = lane & 15;
    int cslot = 2 * w + half;
    const float* Wb = g_Wt + side * 64 + l16 * 4;
    float d0 = 0.f, d1 = 0.f, d2 = 0.f, d3 = 0.f;
#pragma unroll 4
    for (int c = 0; c < CDIM; c++) {
        float f = fsh[cslot][c];
        float4 wv = *(const float4*)(Wb + (size_t)c * 128);
        d0 = fmaf(f, wv.x, d0);
        d1 = fmaf(f, wv.y, d1);
        d2 = fmaf(f, wv.z, d2);
        d3 = fmaf(f, wv.w, d3);
    }
    float m = fmaxf(fmaxf(d0, d1), fmaxf(d2, d3));
#pragma unroll
    for (int o = 8; o > 0; o >>= 1)
        m = fmaxf(m, __shfl_xor_sync(0xFFFFFFFFu, m, o));
    if (l16 == 0) {
        int s = s0 + cslot;
        bool valid = (s < cnt);
        float val = -3.0e38f;
        if (valid) {
            int idx = g_cand[side][s];
            float inv = 1.0f / fmaxf(sqrtf(nrm[cslot]), 1e-8f);
            float sim = m * inv;
            float mv = fminf(fmaxf(M[idx], 0.f), 1.f);
            val = (side == 0) ? (1.0f - sim) * mv : (1.0f - sim) * (1.0f - mv);
        }
        g_cscore[side][s] = val;
    }
}

// ---------------- exact top-256 among candidates (parallel digit pick) ----------------
__global__ void select256_kernel() {
    int side = blockIdx.x, tid = threadIdx.x;   // 256 threads
    const float* sc = g_cscore[side];
    const int* cd = g_cand[side];
    __shared__ unsigned hist[256];
    __shared__ unsigned suf[256];
    __shared__ unsigned sh_pfx, sh_dmask;
    __shared__ int sh_krem, gcnt, tcnt;
    __shared__ int glist[NSEL];
    __shared__ int ties[CAP];

    if (tid == 0) { sh_pfx = 0; sh_dmask = 0; sh_krem = NSEL; }
    __syncthreads();
    for (int shift = 24; shift >= 0; shift -= 8) {
        hist[tid] = 0;
        __syncthreads();
        unsigned dm = sh_dmask, pf = sh_pfx;
        for (int i = tid; i < CAP; i += 256) {
            unsigned key = mapf(sc[i]);
            if ((key & dm) == pf) atomicAdd(&hist[(key >> shift) & 255], 1u);
        }
        __syncthreads();
        suf[tid] = hist[tid];
        __syncthreads();
        for (int o = 1; o < 256; o <<= 1) {
            unsigned add = (tid + o < 256) ? suf[tid + o] : 0u;
            __syncthreads();
            suf[tid] += add;
            __syncthreads();
        }
        unsigned kr = (unsigned)sh_krem;
        if (suf[tid] >= kr && (tid == 255 || suf[tid + 1] < kr)) {
            sh_krem = (int)kr - (int)((tid == 255) ? 0u : suf[tid + 1]);
            sh_pfx   = sh_pfx | ((unsigned)tid << shift);
            sh_dmask = sh_dmask | (0xFFu << shift);
        }
        __syncthreads();
    }
    if (tid == 0) { gcnt = 0; tcnt = 0; }
    __syncthreads();
    unsigned thr = sh_pfx;
    for (int i = tid; i < CAP; i += 256) {
        unsigned key = mapf(sc[i]);
        if (key > thr) {
            int p = atomicAdd(&gcnt, 1);
            if (p < NSEL) glist[p] = cd[i];
        } else if (key == thr) {
            int p = atomicAdd(&tcnt, 1);
            if (p < CAP) ties[p] = cd[i];
        }
    }
    __syncthreads();
    int G = min(gcnt, NSEL);
    for (int e = tid; e < G; e += 256) {
        int pe = glist[e], r = 0;
        for (int j = 0; j < G; j++) r += (glist[j] < pe);
        g_idx[side][r] = pe;
    }
    int need = NSEL - G;
    int T = min(tcnt, CAP);
    for (int e = tid; e < T; e += 256) {
        int pe = ties[e], r = 0;
        for (int j = 0; j < T; j++) r += (ties[j] < pe);
        if (r < need) g_idx[side][G + r] = pe;
    }
}

// ---------------- gather + normalize selected features ----------------
__global__ void gather_kernel(const float* __restrict__ F) {
    int s = blockIdx.x, side = blockIdx.y;
    int idx = g_idx[side][s];
    int n = idx / HW, hw = idx - n * HW;
    const float* base = F + (size_t)n * CDIM * HW + hw;
    int tid = threadIdx.x;  // 128
    float v[4], ss = 0.f;
#pragma unroll
    for (int i = 0; i < 4; i++) {
        int c = tid + i * 128;
        v[i] = base[(size_t)c * HW];
        ss += v[i] * v[i];
    }
#pragma unroll
    for (int o = 16; o > 0; o >>= 1) ss += __shfl_xor_sync(0xFFFFFFFFu, ss, o);
    __shared__ float wsum[4];
    if ((tid & 31) == 0) wsum[tid >> 5] = ss;
    __syncthreads();
    float inv = 1.0f / fmaxf(sqrtf(wsum[0] + wsum[1] + wsum[2] + wsum[3]), 1e-8f);
#pragma unroll
    for (int i = 0; i < 4; i++)
        g_feats[side][s * CDIM + tid + i * 128] = v[i] * inv;
}

__global__ void init_p(const float* __restrict__ fg, const float* __restrict__ bg) {
    int k = blockIdx.x, side = blockIdx.y, c = threadIdx.x;
    const float* src = side ? bg : fg;
    g_p[side][k * CDIM + c] = src[k * CDIM + c];
}

// ---------------- refinement (R11-verified) ----------------
__global__ void assign_kernel() {
    int side = blockIdx.y;
    int s0 = blockIdx.x * 8;
    __shared__ float fsm[8 * CDIM];
    __shared__ float dsm[8][KP];
    int tid = threadIdx.x;  // 256
    const float4* src = (const float4*)(g_feats[side] + s0 * CDIM);
#pragma unroll
    for (int i = 0; i < 4; i++)
        ((float4*)fsm)[tid + 256 * i] = src[tid + 256 * i];
    __syncthreads();
    int j = tid & 63, sg = tid >> 6;
    const float* pj = g_p[side] + j * CDIM;
    const float* fa = fsm + (sg * 2) * CDIM;
    const float* fb = fa + CDIM;
    float d0 = 0.f, d1 = 0.f;
    for (int c = 0; c < CDIM; c += 4) {
        float4 pv = *(const float4*)(pj + c);
        float4 av = *(const float4*)(fa + c);
        float4 bv = *(const float4*)(fb + c);
        d0 = fmaf(av.x, pv.x, fmaf(av.y, pv.y, fmaf(av.z, pv.z, fmaf(av.w, pv.w, d0))));
        d1 = fmaf(bv.x, pv.x, fmaf(bv.y, pv.y, fmaf(bv.z, pv.z, fmaf(bv.w, pv.w, d1))));
    }
    dsm[sg * 2][j] = d0;
    dsm[sg * 2 + 1][j] = d1;
    __syncthreads();
    if (tid < 8) {
        float best = dsm[tid][0];
        int bj = 0;
        for (int jj = 1; jj < KP; jj++) {
            float v = dsm[tid][jj];
            if (v > best) { best = v; bj = jj; }
        }
        g_assign[side][s0 + tid] = bj;
    }
}

__global__ void update_kernel(float step) {
    int k = blockIdx.x, side = blockIdx.y;
    int tid = threadIdx.x;  // 256
    __shared__ int asg[NSEL];
    __shared__ float red[256];
    asg[tid] = g_assign[side][tid];
    __syncthreads();
    int c = tid;
    float s0 = 0.f, s1 = 0.f;
    int cnt = 0;
    for (int s = 0; s < NSEL; s++) {
        if (asg[s] == k) {
            cnt++;
            const float* f = g_feats[side] + s * CDIM;
            s0 += f[c];
            s1 += f[c + 256];
        }
    }
    float denom = fmaxf((float)cnt, 1.0f);
    float p0 = g_p[side][k * CDIM + c];
    float p1 = g_p[side][k * CDIM + c + 256];
    float v0 = (1.0f - step) * p0 + step * (s0 / denom);
    float v1 = (1.0f - step) * p1 + step * (s1 / denom);
    red[tid] = v0 * v0 + v1 * v1;
    __syncthreads();
    for (int o = 128; o > 0; o >>= 1) {
        if (tid < o) red[tid] += red[tid + o];
        __syncthreads();
    }
    float inv = 1.0f / fmaxf(sqrtf(red[0]), 1e-8f);
    if (cnt > 0) {
        g_p[side][k * CDIM + c]       = v0 * inv;
        g_p[side][k * CDIM + c + 256] = v1 * inv;
    }
}

// ---------------- losses ----------------
__global__ void loss_kernel() {
    int s = blockIdx.x;
    int tid = threadIdx.x;  // 256
    __shared__ float posf[CDIM], negf[CDIM], dsm[192];
    posf[tid]       = g_feats[0][s * CDIM + tid];
    posf[tid + 256] = g_feats[0][s * CDIM + tid + 256];
    negf[tid]       = g_feats[1][s * CDIM + tid];
    negf[tid + 256] = g_feats[1][s * CDIM + tid + 256];
    __syncthreads();
    if (tid < 192) {
        int kind = tid / 64, j = tid % 64;
        const float* f = (kind == 2) ? negf : posf;
        const float* p = ((kind == 1) ? g_p[1] : g_p[0]) + j * CDIM;
        float d = 0.f;
        for (int c = 0; c < CDIM; c += 4) {
            float4 pv = *(const float4*)(p + c);
            d = fmaf(f[c], pv.x, fmaf(f[c+1], pv.y, fmaf(f[c+2], pv.z, fmaf(f[c+3], pv.w, d))));
        }
        dsm[tid] = d;
    }
    __syncthreads();
    if (tid == 0) {
        float mp = dsm[0];
        for (int j = 1; j < 64; j++) mp = fmaxf(mp, dsm[j]);
        float mb = dsm[64];
        for (int j = 65; j < 128; j++) mb = fmaxf(mb, dsm[j]);
        float mn = dsm[128];
        for (int j = 129; j < 192; j++) mn = fmaxf(mn, dsm[j]);
        g_simpos[s] = mp;
        g_simneg[s] = mn;
        float a1 = mp / TAU;
        float sum1 = 0.f;
        for (int j = 0; j < 64; j++) sum1 += expf(dsm[j] / TAU - a1);
        float aall = fmaxf(mp, mb) / TAU;
        float sum2 = 0.f;
        for (int j = 0; j < 128; j++) sum2 += expf(dsm[j] / TAU - aall);
        g_info[s] = (aall + logf(sum2)) - (a1 + logf(sum1));
    }
}

__global__ void finalize_kernel(float* __restrict__ out) {
    int tid = threadIdx.x;  // 256
    __shared__ float r1[256], r2[256], r3[256];
    r1[tid] = g_simpos[tid];
    r2[tid] = g_simneg[tid];
    r3[tid] = g_info[tid];
    __syncthreads();
    for (int o = 128; o > 0; o >>= 1) {
        if (tid < o) { r1[tid] += r1[tid+o]; r2[tid] += r2[tid+o]; r3[tid] += r3[tid+o]; }
        __syncthreads();
    }
    if (tid == 0) {
        float mp = r1[0] / (float)NSEL;
        float mn = r2[0] / (float)NSEL;
        float mi = r3[0] / (float)NSEL;
        out[0] = fmaxf(0.f, MARGIN + mn - mp) + 0.25f * mi;
    }
}

__global__ void refined_kernel(const float* __restrict__ fg, const float* __restrict__ bg,
                               float* __restrict__ out) {
    int k = blockIdx.x, side = blockIdx.y, c = threadIdx.x;  // 512 threads
    const float* src = side ? bg : fg;
    float v = (1.0f - MBLEND) * src[k * CDIM + c] + MBLEND * g_p[side][k * CDIM + c];
    __shared__ float red[CDIM];
    red[c] = v * v;
    __syncthreads();
    for (int o = 256; o > 0; o >>= 1) {
        if (c < o) red[c] += red[c + o];
        __syncthreads();
    }
    float inv = 1.0f / fmaxf(sqrtf(red[0]), 1e-8f);
    out[1 + side * (KP * CDIM) + k * CDIM + c] = v * inv;
}

// ---------------- launch ----------------
extern "C" void kernel_launch(void* const* d_in, const int* in_sizes, int n_in,
                              void* d_out, int out_size) {
    const float* fg = (const float*)d_in[0];
    const float* bg = (const float*)d_in[1];
    const float* F  = (const float*)d_in[2];
    const float* M  = (const float*)d_in[3];
    float* out = (float*)d_out;

    cudaFuncSetAttribute(score_tc, cudaFuncAttributeMaxDynamicSharedMemorySize, SCORE_SMEM);

    prep_wt<<<128, 512>>>(fg, bg);
    prep_wb16<<<128, 128>>>(fg, bg);
    zero_aux<<<128, 256>>>();
    score_tc<<<NP / 128, 256, SCORE_SMEM>>>(F, M);
    hist16_kernel<<<dim3(NP / 256, 2), 256>>>();
    pick16_kernel<<<2, 256>>>();
    hist8_kernel<<<dim3(NP / 256, 2), 256>>>();
    pick8_kernel<<<2, 256>>>();
    collect_kernel<<<dim3(NP / 256, 2), 256>>>();
    rescore_kernel<<<dim3(CAP / 16, 2), 256>>>(F, M);
    select256_kernel<<<2, 256>>>();
    gather_kernel<<<dim3(NSEL, 2), 128>>>(F);
    init_p<<<dim3(KP, 2), 512>>>(fg, bg);
    for (int it = 0; it < NREF; it++) {
        float step = 0.1f / (1.0f + 0.5f * (float)it);
        assign_kernel<<<dim3(NSEL / 8, 2), 256>>>();
        update_kernel<<<dim3(KP, 2), 256>>>(step);
    }
    loss_kernel<<<NSEL, 256>>>();
    finalize_kernel<<<1, 256>>>(out);
    refined_kernel<<<dim3(KP, 2), 512>>>(fg, bg, out);
}